// round 14
// baseline (speedup 1.0000x reference)
#include <cuda_runtime.h>
#include <cuda_fp16.h>
#include <math.h>
#include <stdint.h>

// Problem constants (fixed shapes)
#define Lq 4096
#define Dm 1536
#define NH 12
#define HDim 128
#define Cc 64
#define S1c 22
#define S2c 21
#define EPSF 1e-6f

// Scratch (device globals; no runtime allocation allowed)
__device__ __half g_Xh[Lq * Dm];
__device__ __half g_Wc[3 * Dm * Dm];   // Wq | Wk | Wv concatenated along rows
__device__ __half g_Woh[Dm * Dm];
__device__ __half g_Qh[Lq * Dm];
__device__ __half g_Kh[Lq * Dm];
__device__ __half g_Vt[Dm * Lq];       // [d_global][token]
__device__ __half g_Ah[Lq * Dm];

// ---------------------------------------------------------------------------
// Helpers
// ---------------------------------------------------------------------------
__device__ __forceinline__ float ex2f(float x) {
    float y;
    asm("ex2.approx.ftz.f32 %0, %1;" : "=f"(y) : "f"(x));
    return y;
}

__device__ __forceinline__ void mma16(float* c, const uint32_t* a, uint32_t b0, uint32_t b1) {
    asm volatile(
        "mma.sync.aligned.m16n8k16.row.col.f32.f16.f16.f32 "
        "{%0,%1,%2,%3}, {%4,%5,%6,%7}, {%8,%9}, {%0,%1,%2,%3};\n"
        : "+f"(c[0]), "+f"(c[1]), "+f"(c[2]), "+f"(c[3])
        : "r"(a[0]), "r"(a[1]), "r"(a[2]), "r"(a[3]), "r"(b0), "r"(b1));
}

__device__ __forceinline__ void ldsm4(uint32_t& r0, uint32_t& r1, uint32_t& r2,
                                      uint32_t& r3, uint32_t a) {
    asm volatile("ldmatrix.sync.aligned.m8n8.x4.shared.b16 {%0,%1,%2,%3}, [%4];"
                 : "=r"(r0), "=r"(r1), "=r"(r2), "=r"(r3) : "r"(a));
}

__device__ __forceinline__ void cp16(const void* dst_smem, const void* src) {
    uint32_t d = (uint32_t)__cvta_generic_to_shared(dst_smem);
    asm volatile("cp.async.cg.shared.global [%0], [%1], 16;\n" :: "r"(d), "l"(src));
}
#define CP_COMMIT asm volatile("cp.async.commit_group;\n")
#define CP_WAIT(n) asm volatile("cp.async.wait_group %0;\n" :: "n"(n))

__device__ __forceinline__ uint32_t smem_u32(const void* p) {
    return (uint32_t)__cvta_generic_to_shared(p);
}
__device__ __forceinline__ uint32_t ldh2(const __half* p) { return *(const uint32_t*)p; }
__device__ __forceinline__ uint32_t packh2(float a, float b) {
    __half2 h = __floats2half2_rn(a, b);
    return *(uint32_t*)&h;
}

// ---------------------------------------------------------------------------
// fp32 -> fp16 conversion: x + 4 weights in ONE launch (grid.y selects tensor)
// ---------------------------------------------------------------------------
__global__ __launch_bounds__(256) void conv_all(
    const float* __restrict__ x,
    const float* __restrict__ w0, const float* __restrict__ w1,
    const float* __restrict__ w2, const float* __restrict__ w3,
    __half* __restrict__ xo,
    __half* __restrict__ o0, __half* __restrict__ o1,
    __half* __restrict__ o2, __half* __restrict__ o3,
    int nX, int nW)
{
    const float* in; __half* out; int n;
    switch (blockIdx.y) {
        case 0: in = x;  out = xo; n = nX; break;
        case 1: in = w0; out = o0; n = nW; break;
        case 2: in = w1; out = o1; n = nW; break;
        case 3: in = w2; out = o2; n = nW; break;
        default: in = w3; out = o3; n = nW; break;
    }
    int i = (blockIdx.x * 256 + threadIdx.x) * 8;
    if (i < n) {
        float4 v0 = *(const float4*)(in + i);
        float4 v1 = *(const float4*)(in + i + 4);
        uint4 pk;
        pk.x = packh2(v0.x, v0.y); pk.y = packh2(v0.z, v0.w);
        pk.z = packh2(v1.x, v1.y); pk.w = packh2(v1.z, v1.w);
        *(uint4*)(out + i) = pk;
    }
}

// ---------------------------------------------------------------------------
// fp16 GEMM core. mode 0: fp32 row-major out. mode 1: fp16 row-major out.
// mode 2: fp16 TRANSPOSED out to Vt[d][token]. BM=BN=128, BK=32, 8 warps,
// ldmatrix, 5-stage ring (R11 champion schedule).
// ---------------------------------------------------------------------------
#define GSTR 40
#define GTILE (128 * GSTR)
#define GSTAGE (2 * GTILE)
#define NSTG 5
#define G_SMEM (NSTG * GSTAGE * 2)
#define TSTR 136   // transpose-stage stride (halfs)

__device__ __forceinline__ void gemm_body(
    const __half* __restrict__ X, const __half* __restrict__ Wr,
    const float* __restrict__ bias, void* __restrict__ Cout, int mode,
    int m0, int ncol0, __half* smg, __half* __restrict__ VtOut)
{
    const uint32_t sbase = smem_u32(smg);
    const int t = threadIdx.x, lane = t & 31, wid = t >> 5;
    const int g = lane >> 2, t4 = lane & 3;
    const int wm = wid >> 1, wn = wid & 1;

    float acc[2][8][4];
    #pragma unroll
    for (int i = 0; i < 2; i++)
        #pragma unroll
        for (int j = 0; j < 8; j++)
            #pragma unroll
            for (int q = 0; q < 4; q++) acc[i][j][q] = 0.f;

    auto issue = [&](int kt) {
        __half* As = smg + (kt % NSTG) * GSTAGE;
        __half* Bs = As + GTILE;
        const int k0 = kt * 32;
        #pragma unroll
        for (int i = 0; i < 2; i++) {
            int idx = t + i * 256;
            int r = idx >> 2, c = idx & 3;
            cp16(As + r * GSTR + c * 8, X + (size_t)(m0 + r) * Dm + k0 + c * 8);
        }
        #pragma unroll
        for (int i = 0; i < 2; i++) {
            int idx = t + i * 256;
            int r = idx >> 2, c = idx & 3;
            cp16(Bs + r * GSTR + c * 8, Wr + (size_t)r * Dm + k0 + c * 8);
        }
        CP_COMMIT;
    };

    issue(0); issue(1); issue(2); issue(3);

    const uint32_t aOff =
        (uint32_t)(((wm * 32 + (lane & 7) + ((lane >> 3) & 1) * 8) * GSTR +
                    (lane >> 4) * 8) * 2);
    const uint32_t bOff =
        (uint32_t)(((wn * 64 + (lane & 7) + (lane >> 4) * 8) * GSTR +
                    ((lane >> 3) & 1) * 8) * 2);

    const int KT = Dm / 32;
    for (int kt = 0; kt < KT; kt++) {
        if (kt < KT - 3)       CP_WAIT(3);
        else if (kt == KT - 3) CP_WAIT(2);
        else if (kt == KT - 2) CP_WAIT(1);
        else                   CP_WAIT(0);
        __syncthreads();
        const uint32_t stA = sbase + (uint32_t)((kt % NSTG) * GSTAGE * 2);
        const uint32_t stB = stA + GTILE * 2;
        #pragma unroll
        for (int ks = 0; ks < 2; ks++) {
            uint32_t af[2][4], bf[8][2];
            ldsm4(af[0][0], af[0][1], af[0][2], af[0][3], stA + aOff + ks * 32);
            ldsm4(af[1][0], af[1][1], af[1][2], af[1][3],
                  stA + aOff + 16 * GSTR * 2 + ks * 32);
            #pragma unroll
            for (int jj = 0; jj < 4; jj++)
                ldsm4(bf[2 * jj][0], bf[2 * jj][1], bf[2 * jj + 1][0], bf[2 * jj + 1][1],
                      stB + bOff + jj * 16 * GSTR * 2 + ks * 32);
            #pragma unroll
            for (int i = 0; i < 2; i++)
                #pragma unroll
                for (int j = 0; j < 8; j++)
                    mma16(acc[i][j], af[i], bf[j][0], bf[j][1]);
        }
        __syncthreads();
        if (kt + 4 < KT) issue(kt + 4);
    }

    if (mode == 2) {
        __syncthreads();
        __half* Ts = smg;
        #pragma unroll
        for (int j = 0; j < 8; j++) {
            int lc = wn * 64 + j * 8 + 2 * t4;
            float b0 = bias[lc], b1 = bias[lc + 1];
            #pragma unroll
            for (int i = 0; i < 2; i++) {
                int r = wm * 32 + i * 16 + g;
                Ts[lc * TSTR + r]           = __float2half_rn(acc[i][j][0] + b0);
                Ts[(lc + 1) * TSTR + r]     = __float2half_rn(acc[i][j][1] + b1);
                Ts[lc * TSTR + r + 8]       = __float2half_rn(acc[i][j][2] + b0);
                Ts[(lc + 1) * TSTR + r + 8] = __float2half_rn(acc[i][j][3] + b1);
            }
        }
        __syncthreads();
        #pragma unroll
        for (int i = 0; i < 8; i++) {
            int idx = t + i * 256;
            int c = idx >> 4, ch = idx & 15;
            *(uint4*)(VtOut + (size_t)(ncol0 + c) * Lq + m0 + ch * 8) =
                *(const uint4*)(Ts + c * TSTR + ch * 8);
        }
        return;
    }

    #pragma unroll
    for (int j = 0; j < 8; j++) {
        int lc = wn * 64 + j * 8 + 2 * t4;
        float b0 = bias[lc], b1 = bias[lc + 1];
        int col = ncol0 + lc;
        #pragma unroll
        for (int i = 0; i < 2; i++) {
            int row = m0 + wm * 32 + i * 16 + g;
            float c00 = acc[i][j][0] + b0, c01 = acc[i][j][1] + b1;
            float c10 = acc[i][j][2] + b0, c11 = acc[i][j][3] + b1;
            if (mode == 1) {
                __half* C = (__half*)Cout;
                *(__half2*)(C + (size_t)row * Dm + col) = __floats2half2_rn(c00, c01);
                *(__half2*)(C + (size_t)(row + 8) * Dm + col) = __floats2half2_rn(c10, c11);
            } else {
                float* C = (float*)Cout;
                *(float2*)(C + (size_t)row * Dm + col) = make_float2(c00, c01);
                *(float2*)(C + (size_t)(row + 8) * Dm + col) = make_float2(c10, c11);
            }
        }
    }
}

// Fused QKV: grid (3*Dm/128, Lq/128). V segment written transposed to Vt.
__global__ __launch_bounds__(256, 2) void gemm_qkv(
    const __half* __restrict__ X, const __half* __restrict__ Wc,
    const float* __restrict__ bq, const float* __restrict__ bk,
    const float* __restrict__ bv,
    __half* __restrict__ Qh, __half* __restrict__ Kh, __half* __restrict__ Vt)
{
    extern __shared__ __half smg[];
    const int n0g = blockIdx.x * 128;
    const int seg = n0g / Dm;
    const int n0 = n0g - seg * Dm;
    const float* bias = (seg == 0) ? bq : (seg == 1) ? bk : bv;
    if (seg < 2) {
        gemm_body(X, Wc + (size_t)n0g * Dm, bias + n0, seg ? Kh : Qh, 1,
                  blockIdx.y * 128, n0, smg, nullptr);
    } else {
        gemm_body(X, Wc + (size_t)n0g * Dm, bias + n0, nullptr, 2,
                  blockIdx.y * 128, n0, smg, Vt);
    }
}

// Output projection (fp32 out) — BM=128 (R11 config)
__global__ __launch_bounds__(256, 2) void gemm_o(
    const __half* __restrict__ X, const __half* __restrict__ W,
    const float* __restrict__ bias, float* __restrict__ out)
{
    extern __shared__ __half smg[];
    const int n0 = blockIdx.x * 128;
    gemm_body(X, W + (size_t)n0 * Dm, bias + n0, out, 0, blockIdx.y * 128, n0,
              smg, nullptr);
}

// ---------------------------------------------------------------------------
// Single-pass RMSNorm + 3D RoPE; ONE block handles BOTH the Q row and K row.
// ---------------------------------------------------------------------------
__global__ __launch_bounds__(256) void rmsnorm_rope_h(
    __half* __restrict__ Tq, __half* __restrict__ Tk,
    const float* __restrict__ gqv, const float* __restrict__ gkv,
    const float* __restrict__ fcos, const float* __restrict__ fsin,
    const int* __restrict__ pH, const int* __restrict__ pW)
{
    const int row = blockIdx.x;
    const int tid = threadIdx.x;
    const int lane = tid & 31, wid = tid >> 5;
    __shared__ float red[8];

    const int H = *pH, W = *pW;
    const int f = row / (H * W);
    const int hh = (row / W) % H;
    const int ww = row % W;

    float cc[3], ssn[3];
    #pragma unroll
    for (int k = 0; k < 3; k++) {
        int pj = tid + k * 256;
        int j = pj & 63;
        const int coord = (j < S1c) ? f : ((j < S1c + S2c) ? hh : ww);
        cc[k]  = fcos[coord * Cc + j];
        ssn[k] = fsin[coord * Cc + j];
    }

    #pragma unroll
    for (int which = 0; which < 2; which++) {
        __half* p = (which ? Tk : Tq) + (size_t)row * Dm;
        const float* g = which ? gkv : gqv;

        float2 vf[3];
        float ss = 0.f;
        #pragma unroll
        for (int k = 0; k < 3; k++) {
            int pj = tid + k * 256;
            vf[k] = __half22float2(*(const __half2*)(p + 2 * pj));
            ss += vf[k].x * vf[k].x + vf[k].y * vf[k].y;
        }
        #pragma unroll
        for (int off = 16; off >= 1; off >>= 1)
            ss += __shfl_xor_sync(0xffffffffu, ss, off);
        if (lane == 0) red[wid] = ss;
        __syncthreads();
        if (wid == 0) {
            float v = (lane < 8) ? red[lane] : 0.f;
            #pragma unroll
            for (int off = 4; off >= 1; off >>= 1)
                v += __shfl_xor_sync(0xffffffffu, v, off);
            if (lane == 0) red[0] = rsqrtf(v * (1.f / Dm) + EPSF);
        }
        __syncthreads();
        const float rms = red[0];
        __syncthreads();

        #pragma unroll
        for (int k = 0; k < 3; k++) {
            int pj = tid + k * 256;
            float2 gg = *(const float2*)(g + 2 * pj);
            const float xr = vf[k].x * rms * gg.x;
            const float xi = vf[k].y * rms * gg.y;
            *(__half2*)(p + 2 * pj) = __floats2half2_rn(xr * cc[k] - xi * ssn[k],
                                                        xr * ssn[k] + xi * cc[k]);
        }
    }
}

// ---------------------------------------------------------------------------
// Flash attention, fp16 mma, ldmatrix loads. BQ=128, key tile 64, 256 thr.
// SPLIT SCHEDULE: warps 0-3 normal (S; softmax; PV_k); warps 4-7 deferred
// (S; PV_{k-1}; softmax) so each SMSP pairs one softmax-phase warp with one
// mma-phase warp — tensor pipe stays fed during the MUFU/SHFL chain.
// 4-stage ring, issue AFTER barrier (deferred warps read stage (kt-1)%4).
// Per-row arithmetic identical to the normal schedule (bitwise).
// ---------------------------------------------------------------------------
#define KSTR 136
#define VSTR 72
#define FNST 4
#define FL_SMEM ((FNST * 64 * KSTR + FNST * 128 * VSTR) * 2)

__global__ __launch_bounds__(256, 1) void flash_h(
    const __half* __restrict__ Q, const __half* __restrict__ K,
    const __half* __restrict__ Vt, __half* __restrict__ O)
{
    extern __shared__ __half smf[];
    __half* Ks = smf;
    __half* Vs = Ks + FNST * 64 * KSTR;
    const uint32_t sB = smem_u32(smf);

    const int t = threadIdx.x, lane = t & 31, wid = t >> 5;
    const int g = lane >> 2, t4 = lane & 3;
    const bool defer = (wid >= 4);     // SMSP s hosts wid=s (normal) + wid=s+4 (deferred)
    const int head = blockIdx.y;
    const int q0 = blockIdx.x * 128;
    const __half* Qg = Q + (size_t)q0 * Dm + head * HDim;
    const __half* Kg0 = K + head * HDim;
    const __half* Vtg = Vt + (size_t)(head * HDim) * Lq;

    for (int i = t; i < 128 * 16; i += 256) {
        int r = i >> 4, c = i & 15;
        *(uint4*)(Ks + r * KSTR + c * 8) = *(const uint4*)(Qg + (size_t)r * Dm + c * 8);
    }
    __syncthreads();
    uint32_t qf[8][4];
    {
        const __half* bp = Ks + (wid * 16 + g) * KSTR;
        #pragma unroll
        for (int ks = 0; ks < 8; ks++) {
            qf[ks][0] = ldh2(bp + ks * 16 + 2 * t4);
            qf[ks][1] = ldh2(bp + 8 * KSTR + ks * 16 + 2 * t4);
            qf[ks][2] = ldh2(bp + ks * 16 + 2 * t4 + 8);
            qf[ks][3] = ldh2(bp + 8 * KSTR + ks * 16 + 2 * t4 + 8);
        }
    }
    __syncthreads();

    float o[16][4];
    #pragma unroll
    for (int j = 0; j < 16; j++) { o[j][0] = o[j][1] = o[j][2] = o[j][3] = 0.f; }
    float m0 = -1e30f, m1 = -1e30f, l0 = 0.f, l1 = 0.f;
    uint32_t ph[8][2];   // persistent: deferred warps carry P across iterations
    const float KS2 = 0.08838834764831845f * 1.4426950408889634f;

    auto issue = [&](int kt) {
        const int b = kt & (FNST - 1);
        const __half* Kg = Kg0 + (size_t)(kt * 64) * Dm;
        __half* Kd = Ks + b * 64 * KSTR;
        __half* Vd = Vs + b * 128 * VSTR;
        #pragma unroll
        for (int i = 0; i < 4; i++) {
            int idx = t + i * 256;
            int r = idx >> 4, c = idx & 15;
            cp16(Kd + r * KSTR + c * 8, Kg + (size_t)r * Dm + c * 8);
        }
        #pragma unroll
        for (int i = 0; i < 4; i++) {
            int idx = t + i * 256;
            int r = idx >> 3, c = idx & 7;
            cp16(Vd + r * VSTR + c * 8, Vtg + (size_t)r * Lq + kt * 64 + c * 8);
        }
        CP_COMMIT;
    };

    const uint32_t kOff =
        (uint32_t)((((lane & 7) + (lane >> 4) * 8) * KSTR + ((lane >> 3) & 1) * 8) * 2);
    const uint32_t vOff =
        (uint32_t)((((lane & 7) + (lane >> 4) * 8) * VSTR + ((lane >> 3) & 1) * 8) * 2);

    auto pv = [&](int stage) {
        const uint32_t stV = sB + (uint32_t)((FNST * 64 * KSTR + stage * 128 * VSTR) * 2);
        #pragma unroll
        for (int mm = 0; mm < 4; mm++) {
            uint32_t a[4] = { ph[2 * mm][0], ph[2 * mm][1],
                              ph[2 * mm + 1][0], ph[2 * mm + 1][1] };
            #pragma unroll
            for (int jj = 0; jj < 8; jj++) {
                uint32_t v0, v1, v2, v3;
                ldsm4(v0, v1, v2, v3, stV + vOff + jj * 16 * VSTR * 2 + mm * 32);
                mma16(o[2 * jj], a, v0, v1);
                mma16(o[2 * jj + 1], a, v2, v3);
            }
        }
    };

    issue(0); issue(1);
    const int NT = Lq / 64;
    for (int kt = 0; kt < NT; kt++) {
        const int b = kt & (FNST - 1);
        if (kt + 1 < NT) CP_WAIT(1);
        else             CP_WAIT(0);
        __syncthreads();
        if (kt + 2 < NT) issue(kt + 2);   // after barrier: writer (kt+2)%4 disjoint
                                          // from live stages kt%4 and (kt-1)%4

        // S = Q @ K^T : 16 rows x 64 keys per warp
        const uint32_t stK = sB + (uint32_t)(b * 64 * KSTR * 2);
        float s[8][4];
        #pragma unroll
        for (int j = 0; j < 8; j++) { s[j][0] = s[j][1] = s[j][2] = s[j][3] = 0.f; }
        #pragma unroll
        for (int ks = 0; ks < 8; ks++) {
            uint32_t kf[8][2];
            #pragma unroll
            for (int jj = 0; jj < 4; jj++)
                ldsm4(kf[2 * jj][0], kf[2 * jj][1], kf[2 * jj + 1][0], kf[2 * jj + 1][1],
                      stK + kOff + jj * 16 * KSTR * 2 + ks * 32);
            #pragma unroll
            for (int j = 0; j < 8; j++)
                mma16(s[j], qf[ks], kf[j][0], kf[j][1]);
        }

        // Deferred warps: apply PV of the PREVIOUS tile (o still in scale m_{k-1})
        if (defer && kt > 0) pv((kt - 1) & (FNST - 1));

        // Online softmax; P packed to register fragments (overwrites ph)
        float mx0 = -1e30f, mx1 = -1e30f;
        #pragma unroll
        for (int j = 0; j < 8; j++) {
            mx0 = fmaxf(mx0, fmaxf(s[j][0], s[j][1]));
            mx1 = fmaxf(mx1, fmaxf(s[j][2], s[j][3]));
        }
        mx0 *= KS2; mx1 *= KS2;
        mx0 = fmaxf(mx0, __shfl_xor_sync(0xffffffffu, mx0, 1));
        mx0 = fmaxf(mx0, __shfl_xor_sync(0xffffffffu, mx0, 2));
        mx1 = fmaxf(mx1, __shfl_xor_sync(0xffffffffu, mx1, 1));
        mx1 = fmaxf(mx1, __shfl_xor_sync(0xffffffffu, mx1, 2));
        float nm0 = fmaxf(m0, mx0), nm1 = fmaxf(m1, mx1);
        float corr0 = ex2f(m0 - nm0), corr1 = ex2f(m1 - nm1);
        m0 = nm0; m1 = nm1;
        float r0 = 0.f, r1 = 0.f;
        #pragma unroll
        for (int j = 0; j < 8; j++) {
            float p00 = ex2f(s[j][0] * KS2 - m0);
            float p01 = ex2f(s[j][1] * KS2 - m0);
            float p10 = ex2f(s[j][2] * KS2 - m1);
            float p11 = ex2f(s[j][3] * KS2 - m1);
            r0 += p00 + p01; r1 += p10 + p11;
            ph[j][0] = packh2(p00, p01);
            ph[j][1] = packh2(p10, p11);
        }
        r0 += __shfl_xor_sync(0xffffffffu, r0, 1);
        r0 += __shfl_xor_sync(0xffffffffu, r0, 2);
        r1 += __shfl_xor_sync(0xffffffffu, r1, 1);
        r1 += __shfl_xor_sync(0xffffffffu, r1, 2);
        l0 = l0 * corr0 + r0;
        l1 = l1 * corr1 + r1;
        #pragma unroll
        for (int j = 0; j < 16; j++) {
            o[j][0] *= corr0; o[j][1] *= corr0;
            o[j][2] *= corr1; o[j][3] *= corr1;
        }

        // Normal warps: apply PV of the CURRENT tile
        if (!defer) pv(b);
    }
    // Deferred warps owe the last tile's PV (stage untouched after loop)
    if (defer) pv((NT - 1) & (FNST - 1));

    const float inv0 = 1.f / l0, inv1 = 1.f / l1;
    __half* O0 = O + (size_t)(q0 + wid * 16 + g) * Dm + head * HDim + 2 * t4;
    __half* O1 = O0 + 8 * (size_t)Dm;
    #pragma unroll
    for (int j = 0; j < 16; j++) {
        *(__half2*)(O0 + j * 8) = __floats2half2_rn(o[j][0] * inv0, o[j][1] * inv0);
        *(__half2*)(O1 + j * 8) = __floats2half2_rn(o[j][2] * inv1, o[j][3] * inv1);
    }
}

// ---------------------------------------------------------------------------
// Launch
// ---------------------------------------------------------------------------
extern "C" void kernel_launch(void* const* d_in, const int* in_sizes, int n_in,
                              void* d_out, int out_size)
{
    const float* x    = (const float*)d_in[0];
    const float* wq   = (const float*)d_in[1];
    const float* wk   = (const float*)d_in[2];
    const float* wv   = (const float*)d_in[3];
    const float* wo   = (const float*)d_in[4];
    const float* bq   = (const float*)d_in[5];
    const float* bk   = (const float*)d_in[6];
    const float* bv   = (const float*)d_in[7];
    const float* bo   = (const float*)d_in[8];
    const float* gq   = (const float*)d_in[9];
    const float* gk   = (const float*)d_in[10];
    const float* fcos = (const float*)d_in[11];
    const float* fsin = (const float*)d_in[12];
    // d_in[13] = seq_lens (all == L)
    const int* pH = (const int*)d_in[15];
    const int* pW = (const int*)d_in[16];
    float* out = (float*)d_out;

    __half *Xh, *Wc, *Woh, *Qh, *Kh, *Vt, *Ah;
    cudaGetSymbolAddress((void**)&Xh, g_Xh);
    cudaGetSymbolAddress((void**)&Wc, g_Wc);
    cudaGetSymbolAddress((void**)&Woh, g_Woh);
    cudaGetSymbolAddress((void**)&Qh, g_Qh);
    cudaGetSymbolAddress((void**)&Kh, g_Kh);
    cudaGetSymbolAddress((void**)&Vt, g_Vt);
    cudaGetSymbolAddress((void**)&Ah, g_Ah);

    cudaFuncSetAttribute(gemm_qkv, cudaFuncAttributeMaxDynamicSharedMemorySize, G_SMEM);
    cudaFuncSetAttribute(gemm_o, cudaFuncAttributeMaxDynamicSharedMemorySize, G_SMEM);
    cudaFuncSetAttribute(flash_h, cudaFuncAttributeMaxDynamicSharedMemorySize, FL_SMEM);

    const int nX = Lq * Dm, nW = Dm * Dm;
    conv_all<<<dim3(nX / 8 / 256, 5), 256>>>(
        x, wq, wk, wv, wo, Xh,
        Wc, Wc + (size_t)Dm * Dm, Wc + 2 * (size_t)Dm * Dm, Woh, nX, nW);

    gemm_qkv<<<dim3(3 * Dm / 128, Lq / 128), 256, G_SMEM>>>(
        Xh, Wc, bq, bk, bv, Qh, Kh, Vt);

    rmsnorm_rope_h<<<Lq, 256>>>(Qh, Kh, gq, gk, fcos, fsin, pH, pW);

    flash_h<<<dim3(Lq / 128, NH), 256, FL_SMEM>>>(Qh, Kh, Vt, Ah);

    gemm_o<<<dim3(Dm / 128, Lq / 128), 256, G_SMEM>>>(Ah, Woh, bo, out);
}

// round 15
// speedup vs baseline: 1.0586x; 1.0586x over previous
#include <cuda_runtime.h>
#include <cuda_fp16.h>
#include <math.h>
#include <stdint.h>

// Problem constants (fixed shapes)
#define Lq 4096
#define Dm 1536
#define NH 12
#define HDim 128
#define Cc 64
#define S1c 22
#define S2c 21
#define EPSF 1e-6f

// Scratch (device globals; no runtime allocation allowed)
__device__ __half g_Xh[Lq * Dm];
__device__ __half g_Wc[3 * Dm * Dm];   // Wq | Wk | Wv concatenated along rows
__device__ __half g_Woh[Dm * Dm];
__device__ __half g_Qh[Lq * Dm];
__device__ __half g_Kh[Lq * Dm];
__device__ __half g_Vt[Dm * Lq];       // [d_global][token]
__device__ __half g_Ah[Lq * Dm];

// ---------------------------------------------------------------------------
// Helpers
// ---------------------------------------------------------------------------
__device__ __forceinline__ float ex2f(float x) {
    float y;
    asm("ex2.approx.ftz.f32 %0, %1;" : "=f"(y) : "f"(x));
    return y;
}

__device__ __forceinline__ void mma16(float* c, const uint32_t* a, uint32_t b0, uint32_t b1) {
    asm volatile(
        "mma.sync.aligned.m16n8k16.row.col.f32.f16.f16.f32 "
        "{%0,%1,%2,%3}, {%4,%5,%6,%7}, {%8,%9}, {%0,%1,%2,%3};\n"
        : "+f"(c[0]), "+f"(c[1]), "+f"(c[2]), "+f"(c[3])
        : "r"(a[0]), "r"(a[1]), "r"(a[2]), "r"(a[3]), "r"(b0), "r"(b1));
}

__device__ __forceinline__ void ldsm4(uint32_t& r0, uint32_t& r1, uint32_t& r2,
                                      uint32_t& r3, uint32_t a) {
    asm volatile("ldmatrix.sync.aligned.m8n8.x4.shared.b16 {%0,%1,%2,%3}, [%4];"
                 : "=r"(r0), "=r"(r1), "=r"(r2), "=r"(r3) : "r"(a));
}

__device__ __forceinline__ void cp16(const void* dst_smem, const void* src) {
    uint32_t d = (uint32_t)__cvta_generic_to_shared(dst_smem);
    asm volatile("cp.async.cg.shared.global [%0], [%1], 16;\n" :: "r"(d), "l"(src));
}
#define CP_COMMIT asm volatile("cp.async.commit_group;\n")
#define CP_WAIT(n) asm volatile("cp.async.wait_group %0;\n" :: "n"(n))

__device__ __forceinline__ uint32_t smem_u32(const void* p) {
    return (uint32_t)__cvta_generic_to_shared(p);
}
__device__ __forceinline__ uint32_t ldh2(const __half* p) { return *(const uint32_t*)p; }
__device__ __forceinline__ uint32_t packh2(float a, float b) {
    __half2 h = __floats2half2_rn(a, b);
    return *(uint32_t*)&h;
}

// ---------------------------------------------------------------------------
// fp32 -> fp16 conversion: x + 4 weights in ONE launch (grid.y selects tensor)
// ---------------------------------------------------------------------------
__global__ __launch_bounds__(256) void conv_all(
    const float* __restrict__ x,
    const float* __restrict__ w0, const float* __restrict__ w1,
    const float* __restrict__ w2, const float* __restrict__ w3,
    __half* __restrict__ xo,
    __half* __restrict__ o0, __half* __restrict__ o1,
    __half* __restrict__ o2, __half* __restrict__ o3,
    int nX, int nW)
{
    const float* in; __half* out; int n;
    switch (blockIdx.y) {
        case 0: in = x;  out = xo; n = nX; break;
        case 1: in = w0; out = o0; n = nW; break;
        case 2: in = w1; out = o1; n = nW; break;
        case 3: in = w2; out = o2; n = nW; break;
        default: in = w3; out = o3; n = nW; break;
    }
    int i = (blockIdx.x * 256 + threadIdx.x) * 8;
    if (i < n) {
        float4 v0 = *(const float4*)(in + i);
        float4 v1 = *(const float4*)(in + i + 4);
        uint4 pk;
        pk.x = packh2(v0.x, v0.y); pk.y = packh2(v0.z, v0.w);
        pk.z = packh2(v1.x, v1.y); pk.w = packh2(v1.z, v1.w);
        *(uint4*)(out + i) = pk;
    }
}

// ---------------------------------------------------------------------------
// fp16 GEMM core (QKV path). mode 1: fp16 row-major out. mode 2: transposed
// fp16 out to Vt. BM=BN=128, BK=32, 8 warps, ldmatrix, 5-stage ring.
// (R11 champion — unchanged)
// ---------------------------------------------------------------------------
#define GSTR 40
#define GTILE (128 * GSTR)
#define GSTAGE (2 * GTILE)
#define NSTG 5
#define G_SMEM (NSTG * GSTAGE * 2)
#define TSTR 136   // transpose-stage stride (halfs)

__device__ __forceinline__ void gemm_body(
    const __half* __restrict__ X, const __half* __restrict__ Wr,
    const float* __restrict__ bias, void* __restrict__ Cout, int mode,
    int m0, int ncol0, __half* smg, __half* __restrict__ VtOut)
{
    const uint32_t sbase = smem_u32(smg);
    const int t = threadIdx.x, lane = t & 31, wid = t >> 5;
    const int g = lane >> 2, t4 = lane & 3;
    const int wm = wid >> 1, wn = wid & 1;

    float acc[2][8][4];
    #pragma unroll
    for (int i = 0; i < 2; i++)
        #pragma unroll
        for (int j = 0; j < 8; j++)
            #pragma unroll
            for (int q = 0; q < 4; q++) acc[i][j][q] = 0.f;

    auto issue = [&](int kt) {
        __half* As = smg + (kt % NSTG) * GSTAGE;
        __half* Bs = As + GTILE;
        const int k0 = kt * 32;
        #pragma unroll
        for (int i = 0; i < 2; i++) {
            int idx = t + i * 256;
            int r = idx >> 2, c = idx & 3;
            cp16(As + r * GSTR + c * 8, X + (size_t)(m0 + r) * Dm + k0 + c * 8);
        }
        #pragma unroll
        for (int i = 0; i < 2; i++) {
            int idx = t + i * 256;
            int r = idx >> 2, c = idx & 3;
            cp16(Bs + r * GSTR + c * 8, Wr + (size_t)r * Dm + k0 + c * 8);
        }
        CP_COMMIT;
    };

    issue(0); issue(1); issue(2); issue(3);

    const uint32_t aOff =
        (uint32_t)(((wm * 32 + (lane & 7) + ((lane >> 3) & 1) * 8) * GSTR +
                    (lane >> 4) * 8) * 2);
    const uint32_t bOff =
        (uint32_t)(((wn * 64 + (lane & 7) + (lane >> 4) * 8) * GSTR +
                    ((lane >> 3) & 1) * 8) * 2);

    const int KT = Dm / 32;
    for (int kt = 0; kt < KT; kt++) {
        if (kt < KT - 3)       CP_WAIT(3);
        else if (kt == KT - 3) CP_WAIT(2);
        else if (kt == KT - 2) CP_WAIT(1);
        else                   CP_WAIT(0);
        __syncthreads();
        const uint32_t stA = sbase + (uint32_t)((kt % NSTG) * GSTAGE * 2);
        const uint32_t stB = stA + GTILE * 2;
        #pragma unroll
        for (int ks = 0; ks < 2; ks++) {
            uint32_t af[2][4], bf[8][2];
            ldsm4(af[0][0], af[0][1], af[0][2], af[0][3], stA + aOff + ks * 32);
            ldsm4(af[1][0], af[1][1], af[1][2], af[1][3],
                  stA + aOff + 16 * GSTR * 2 + ks * 32);
            #pragma unroll
            for (int jj = 0; jj < 4; jj++)
                ldsm4(bf[2 * jj][0], bf[2 * jj][1], bf[2 * jj + 1][0], bf[2 * jj + 1][1],
                      stB + bOff + jj * 16 * GSTR * 2 + ks * 32);
            #pragma unroll
            for (int i = 0; i < 2; i++)
                #pragma unroll
                for (int j = 0; j < 8; j++)
                    mma16(acc[i][j], af[i], bf[j][0], bf[j][1]);
        }
        __syncthreads();
        if (kt + 4 < KT) issue(kt + 4);
    }

    if (mode == 2) {
        __syncthreads();
        __half* Ts = smg;
        #pragma unroll
        for (int j = 0; j < 8; j++) {
            int lc = wn * 64 + j * 8 + 2 * t4;
            float b0 = bias[lc], b1 = bias[lc + 1];
            #pragma unroll
            for (int i = 0; i < 2; i++) {
                int r = wm * 32 + i * 16 + g;
                Ts[lc * TSTR + r]           = __float2half_rn(acc[i][j][0] + b0);
                Ts[(lc + 1) * TSTR + r]     = __float2half_rn(acc[i][j][1] + b1);
                Ts[lc * TSTR + r + 8]       = __float2half_rn(acc[i][j][2] + b0);
                Ts[(lc + 1) * TSTR + r + 8] = __float2half_rn(acc[i][j][3] + b1);
            }
        }
        __syncthreads();
        #pragma unroll
        for (int i = 0; i < 8; i++) {
            int idx = t + i * 256;
            int c = idx >> 4, ch = idx & 15;
            *(uint4*)(VtOut + (size_t)(ncol0 + c) * Lq + m0 + ch * 8) =
                *(const uint4*)(Ts + c * TSTR + ch * 8);
        }
        return;
    }

    #pragma unroll
    for (int j = 0; j < 8; j++) {
        int lc = wn * 64 + j * 8 + 2 * t4;
        float b0 = bias[lc], b1 = bias[lc + 1];
        int col = ncol0 + lc;
        #pragma unroll
        for (int i = 0; i < 2; i++) {
            int row = m0 + wm * 32 + i * 16 + g;
            float c00 = acc[i][j][0] + b0, c01 = acc[i][j][1] + b1;
            float c10 = acc[i][j][2] + b0, c11 = acc[i][j][3] + b1;
            __half* C = (__half*)Cout;
            *(__half2*)(C + (size_t)row * Dm + col) = __floats2half2_rn(c00, c01);
            *(__half2*)(C + (size_t)(row + 8) * Dm + col) = __floats2half2_rn(c10, c11);
        }
    }
}

// Fused QKV: grid (3*Dm/128, Lq/128). V segment written transposed to Vt.
__global__ __launch_bounds__(256, 2) void gemm_qkv(
    const __half* __restrict__ X, const __half* __restrict__ Wc,
    const float* __restrict__ bq, const float* __restrict__ bk,
    const float* __restrict__ bv,
    __half* __restrict__ Qh, __half* __restrict__ Kh, __half* __restrict__ Vt)
{
    extern __shared__ __half smg[];
    const int n0g = blockIdx.x * 128;
    const int seg = n0g / Dm;
    const int n0 = n0g - seg * Dm;
    const float* bias = (seg == 0) ? bq : (seg == 1) ? bk : bv;
    if (seg < 2) {
        gemm_body(X, Wc + (size_t)n0g * Dm, bias + n0, seg ? Kh : Qh, 1,
                  blockIdx.y * 128, n0, smg, nullptr);
    } else {
        gemm_body(X, Wc + (size_t)n0g * Dm, bias + n0, nullptr, 2,
                  blockIdx.y * 128, n0, smg, Vt);
    }
}

// ---------------------------------------------------------------------------
// Output projection, fp32 out. 4 warps (2m x 2n), CTA tile 64x128 — SAME
// 32x64 warp tile and inner loop as the champion, but half-height CTAs at
// 4/SM kill the 1.3-wave quantization loss. NSTG=3 ring, depth-2 prefetch.
// ---------------------------------------------------------------------------
#define OSTG ((64 + 128) * GSTR)      // halfs per stage
#define ONST 3
#define O_SMEM (ONST * OSTG * 2)      // 46080 bytes

__global__ __launch_bounds__(128, 4) void gemm_o4(
    const __half* __restrict__ X, const __half* __restrict__ W,
    const float* __restrict__ bias, float* __restrict__ out)
{
    extern __shared__ __half smg[];
    const uint32_t sbase = smem_u32(smg);
    const int t = threadIdx.x, lane = t & 31, wid = t >> 5;   // 4 warps
    const int g = lane >> 2, t4 = lane & 3;
    const int wm = wid >> 1, wn = wid & 1;
    const int n0 = blockIdx.x * 128;
    const int m0 = blockIdx.y * 64;
    const __half* Wr = W + (size_t)n0 * Dm;

    float acc[2][8][4];
    #pragma unroll
    for (int i = 0; i < 2; i++)
        #pragma unroll
        for (int j = 0; j < 8; j++)
            #pragma unroll
            for (int q = 0; q < 4; q++) acc[i][j][q] = 0.f;

    auto issue = [&](int kt) {
        __half* As = smg + (kt % ONST) * OSTG;
        __half* Bs = As + 64 * GSTR;
        const int k0 = kt * 32;
        #pragma unroll
        for (int i = 0; i < 2; i++) {          // A: 64 rows x 4 chunks = 256
            int idx = t + i * 128;
            int r = idx >> 2, c = idx & 3;
            cp16(As + r * GSTR + c * 8, X + (size_t)(m0 + r) * Dm + k0 + c * 8);
        }
        #pragma unroll
        for (int i = 0; i < 4; i++) {          // B: 128 rows x 4 chunks = 512
            int idx = t + i * 128;
            int r = idx >> 2, c = idx & 3;
            cp16(Bs + r * GSTR + c * 8, Wr + (size_t)r * Dm + k0 + c * 8);
        }
        CP_COMMIT;
    };

    issue(0); issue(1);

    const uint32_t aOff =
        (uint32_t)(((wm * 32 + (lane & 7) + ((lane >> 3) & 1) * 8) * GSTR +
                    (lane >> 4) * 8) * 2);
    const uint32_t bOff =
        (uint32_t)(((wn * 64 + (lane & 7) + (lane >> 4) * 8) * GSTR +
                    ((lane >> 3) & 1) * 8) * 2);

    const int KT = Dm / 32;
    for (int kt = 0; kt < KT; kt++) {
        if (kt < KT - 1) CP_WAIT(1);           // group kt done (kt+1 may be pending)
        else             CP_WAIT(0);
        __syncthreads();
        const uint32_t stA = sbase + (uint32_t)((kt % ONST) * OSTG * 2);
        const uint32_t stB = stA + 64 * GSTR * 2;
        #pragma unroll
        for (int ks = 0; ks < 2; ks++) {
            uint32_t af[2][4], bf[8][2];
            ldsm4(af[0][0], af[0][1], af[0][2], af[0][3], stA + aOff + ks * 32);
            ldsm4(af[1][0], af[1][1], af[1][2], af[1][3],
                  stA + aOff + 16 * GSTR * 2 + ks * 32);
            #pragma unroll
            for (int jj = 0; jj < 4; jj++)
                ldsm4(bf[2 * jj][0], bf[2 * jj][1], bf[2 * jj + 1][0], bf[2 * jj + 1][1],
                      stB + bOff + jj * 16 * GSTR * 2 + ks * 32);
            #pragma unroll
            for (int i = 0; i < 2; i++)
                #pragma unroll
                for (int j = 0; j < 8; j++)
                    mma16(acc[i][j], af[i], bf[j][0], bf[j][1]);
        }
        __syncthreads();
        if (kt + 2 < KT) issue(kt + 2);   // writer (kt+2)%3 == (kt-1)%3: its readers
                                          // finished before iter kt-1's 2nd barrier
    }

    #pragma unroll
    for (int j = 0; j < 8; j++) {
        int lc = wn * 64 + j * 8 + 2 * t4;
        float b0 = bias[n0 + lc], b1 = bias[n0 + lc + 1];
        int col = n0 + lc;
        #pragma unroll
        for (int i = 0; i < 2; i++) {
            int row = m0 + wm * 32 + i * 16 + g;
            *(float2*)(out + (size_t)row * Dm + col) =
                make_float2(acc[i][j][0] + b0, acc[i][j][1] + b1);
            *(float2*)(out + (size_t)(row + 8) * Dm + col) =
                make_float2(acc[i][j][2] + b0, acc[i][j][3] + b1);
        }
    }
}

// ---------------------------------------------------------------------------
// Single-pass RMSNorm + 3D RoPE; ONE block handles BOTH the Q row and K row.
// ---------------------------------------------------------------------------
__global__ __launch_bounds__(256) void rmsnorm_rope_h(
    __half* __restrict__ Tq, __half* __restrict__ Tk,
    const float* __restrict__ gqv, const float* __restrict__ gkv,
    const float* __restrict__ fcos, const float* __restrict__ fsin,
    const int* __restrict__ pH, const int* __restrict__ pW)
{
    const int row = blockIdx.x;
    const int tid = threadIdx.x;
    const int lane = tid & 31, wid = tid >> 5;
    __shared__ float red[8];

    const int H = *pH, W = *pW;
    const int f = row / (H * W);
    const int hh = (row / W) % H;
    const int ww = row % W;

    float cc[3], ssn[3];
    #pragma unroll
    for (int k = 0; k < 3; k++) {
        int pj = tid + k * 256;
        int j = pj & 63;
        const int coord = (j < S1c) ? f : ((j < S1c + S2c) ? hh : ww);
        cc[k]  = fcos[coord * Cc + j];
        ssn[k] = fsin[coord * Cc + j];
    }

    #pragma unroll
    for (int which = 0; which < 2; which++) {
        __half* p = (which ? Tk : Tq) + (size_t)row * Dm;
        const float* g = which ? gkv : gqv;

        float2 vf[3];
        float ss = 0.f;
        #pragma unroll
        for (int k = 0; k < 3; k++) {
            int pj = tid + k * 256;
            vf[k] = __half22float2(*(const __half2*)(p + 2 * pj));
            ss += vf[k].x * vf[k].x + vf[k].y * vf[k].y;
        }
        #pragma unroll
        for (int off = 16; off >= 1; off >>= 1)
            ss += __shfl_xor_sync(0xffffffffu, ss, off);
        if (lane == 0) red[wid] = ss;
        __syncthreads();
        if (wid == 0) {
            float v = (lane < 8) ? red[lane] : 0.f;
            #pragma unroll
            for (int off = 4; off >= 1; off >>= 1)
                v += __shfl_xor_sync(0xffffffffu, v, off);
            if (lane == 0) red[0] = rsqrtf(v * (1.f / Dm) + EPSF);
        }
        __syncthreads();
        const float rms = red[0];
        __syncthreads();

        #pragma unroll
        for (int k = 0; k < 3; k++) {
            int pj = tid + k * 256;
            float2 gg = *(const float2*)(g + 2 * pj);
            const float xr = vf[k].x * rms * gg.x;
            const float xi = vf[k].y * rms * gg.y;
            *(__half2*)(p + 2 * pj) = __floats2half2_rn(xr * cc[k] - xi * ssn[k],
                                                        xr * ssn[k] + xi * cc[k]);
        }
    }
}

// ---------------------------------------------------------------------------
// Flash attention — R11 champion, FROZEN (at the mma.sync ceiling).
// ---------------------------------------------------------------------------
#define KSTR 136
#define VSTR 72
#define FNST 4
#define FL_SMEM ((FNST * 64 * KSTR + FNST * 128 * VSTR) * 2)

__global__ __launch_bounds__(256, 1) void flash_h(
    const __half* __restrict__ Q, const __half* __restrict__ K,
    const __half* __restrict__ Vt, __half* __restrict__ O)
{
    extern __shared__ __half smf[];
    __half* Ks = smf;
    __half* Vs = Ks + FNST * 64 * KSTR;
    const uint32_t sB = smem_u32(smf);

    const int t = threadIdx.x, lane = t & 31, wid = t >> 5;
    const int g = lane >> 2, t4 = lane & 3;
    const int head = blockIdx.y;
    const int q0 = blockIdx.x * 128;
    const __half* Qg = Q + (size_t)q0 * Dm + head * HDim;
    const __half* Kg0 = K + head * HDim;
    const __half* Vtg = Vt + (size_t)(head * HDim) * Lq;

    for (int i = t; i < 128 * 16; i += 256) {
        int r = i >> 4, c = i & 15;
        *(uint4*)(Ks + r * KSTR + c * 8) = *(const uint4*)(Qg + (size_t)r * Dm + c * 8);
    }
    __syncthreads();
    uint32_t qf[8][4];
    {
        const __half* bp = Ks + (wid * 16 + g) * KSTR;
        #pragma unroll
        for (int ks = 0; ks < 8; ks++) {
            qf[ks][0] = ldh2(bp + ks * 16 + 2 * t4);
            qf[ks][1] = ldh2(bp + 8 * KSTR + ks * 16 + 2 * t4);
            qf[ks][2] = ldh2(bp + ks * 16 + 2 * t4 + 8);
            qf[ks][3] = ldh2(bp + 8 * KSTR + ks * 16 + 2 * t4 + 8);
        }
    }
    __syncthreads();

    float o[16][4];
    #pragma unroll
    for (int j = 0; j < 16; j++) { o[j][0] = o[j][1] = o[j][2] = o[j][3] = 0.f; }
    float m0 = -1e30f, m1 = -1e30f, l0 = 0.f, l1 = 0.f;
    const float KS2 = 0.08838834764831845f * 1.4426950408889634f;

    auto issue = [&](int kt) {
        const int b = kt & (FNST - 1);
        const __half* Kg = Kg0 + (size_t)(kt * 64) * Dm;
        __half* Kd = Ks + b * 64 * KSTR;
        __half* Vd = Vs + b * 128 * VSTR;
        #pragma unroll
        for (int i = 0; i < 4; i++) {
            int idx = t + i * 256;
            int r = idx >> 4, c = idx & 15;
            cp16(Kd + r * KSTR + c * 8, Kg + (size_t)r * Dm + c * 8);
        }
        #pragma unroll
        for (int i = 0; i < 4; i++) {
            int idx = t + i * 256;
            int r = idx >> 3, c = idx & 7;
            cp16(Vd + r * VSTR + c * 8, Vtg + (size_t)r * Lq + kt * 64 + c * 8);
        }
        CP_COMMIT;
    };

    const uint32_t kOff =
        (uint32_t)((((lane & 7) + (lane >> 4) * 8) * KSTR + ((lane >> 3) & 1) * 8) * 2);
    const uint32_t vOff =
        (uint32_t)((((lane & 7) + (lane >> 4) * 8) * VSTR + ((lane >> 3) & 1) * 8) * 2);

    issue(0); issue(1);
    const int NT = Lq / 64;
    for (int kt = 0; kt < NT; kt++) {
        const int b = kt & (FNST - 1);
        if (kt + 2 < NT) { issue(kt + 2); CP_WAIT(2); }
        else if (kt + 1 < NT) { CP_WAIT(1); }
        else { CP_WAIT(0); }
        __syncthreads();

        const uint32_t stK = sB + (uint32_t)(b * 64 * KSTR * 2);
        const uint32_t stV = sB + (uint32_t)((FNST * 64 * KSTR + b * 128 * VSTR) * 2);

        float s[8][4];
        #pragma unroll
        for (int j = 0; j < 8; j++) { s[j][0] = s[j][1] = s[j][2] = s[j][3] = 0.f; }
        #pragma unroll
        for (int ks = 0; ks < 8; ks++) {
            uint32_t kf[8][2];
            #pragma unroll
            for (int jj = 0; jj < 4; jj++)
                ldsm4(kf[2 * jj][0], kf[2 * jj][1], kf[2 * jj + 1][0], kf[2 * jj + 1][1],
                      stK + kOff + jj * 16 * KSTR * 2 + ks * 32);
            #pragma unroll
            for (int j = 0; j < 8; j++)
                mma16(s[j], qf[ks], kf[j][0], kf[j][1]);
        }

        float mx0 = -1e30f, mx1 = -1e30f;
        #pragma unroll
        for (int j = 0; j < 8; j++) {
            mx0 = fmaxf(mx0, fmaxf(s[j][0], s[j][1]));
            mx1 = fmaxf(mx1, fmaxf(s[j][2], s[j][3]));
        }
        mx0 *= KS2; mx1 *= KS2;
        mx0 = fmaxf(mx0, __shfl_xor_sync(0xffffffffu, mx0, 1));
        mx0 = fmaxf(mx0, __shfl_xor_sync(0xffffffffu, mx0, 2));
        mx1 = fmaxf(mx1, __shfl_xor_sync(0xffffffffu, mx1, 1));
        mx1 = fmaxf(mx1, __shfl_xor_sync(0xffffffffu, mx1, 2));
        float nm0 = fmaxf(m0, mx0), nm1 = fmaxf(m1, mx1);
        float corr0 = ex2f(m0 - nm0), corr1 = ex2f(m1 - nm1);
        m0 = nm0; m1 = nm1;
        float r0 = 0.f, r1 = 0.f;
        uint32_t ph[8][2];
        #pragma unroll
        for (int j = 0; j < 8; j++) {
            float p00 = ex2f(s[j][0] * KS2 - m0);
            float p01 = ex2f(s[j][1] * KS2 - m0);
            float p10 = ex2f(s[j][2] * KS2 - m1);
            float p11 = ex2f(s[j][3] * KS2 - m1);
            r0 += p00 + p01; r1 += p10 + p11;
            ph[j][0] = packh2(p00, p01);
            ph[j][1] = packh2(p10, p11);
        }
        r0 += __shfl_xor_sync(0xffffffffu, r0, 1);
        r0 += __shfl_xor_sync(0xffffffffu, r0, 2);
        r1 += __shfl_xor_sync(0xffffffffu, r1, 1);
        r1 += __shfl_xor_sync(0xffffffffu, r1, 2);
        l0 = l0 * corr0 + r0;
        l1 = l1 * corr1 + r1;
        #pragma unroll
        for (int j = 0; j < 16; j++) {
            o[j][0] *= corr0; o[j][1] *= corr0;
            o[j][2] *= corr1; o[j][3] *= corr1;
        }

        #pragma unroll
        for (int mm = 0; mm < 4; mm++) {
            uint32_t a[4] = { ph[2 * mm][0], ph[2 * mm][1],
                              ph[2 * mm + 1][0], ph[2 * mm + 1][1] };
            #pragma unroll
            for (int jj = 0; jj < 8; jj++) {
                uint32_t v0, v1, v2, v3;
                ldsm4(v0, v1, v2, v3, stV + vOff + jj * 16 * VSTR * 2 + mm * 32);
                mma16(o[2 * jj], a, v0, v1);
                mma16(o[2 * jj + 1], a, v2, v3);
            }
        }
    }

    const float inv0 = 1.f / l0, inv1 = 1.f / l1;
    __half* O0 = O + (size_t)(q0 + wid * 16 + g) * Dm + head * HDim + 2 * t4;
    __half* O1 = O0 + 8 * (size_t)Dm;
    #pragma unroll
    for (int j = 0; j < 16; j++) {
        *(__half2*)(O0 + j * 8) = __floats2half2_rn(o[j][0] * inv0, o[j][1] * inv0);
        *(__half2*)(O1 + j * 8) = __floats2half2_rn(o[j][2] * inv1, o[j][3] * inv1);
    }
}

// ---------------------------------------------------------------------------
// Launch
// ---------------------------------------------------------------------------
extern "C" void kernel_launch(void* const* d_in, const int* in_sizes, int n_in,
                              void* d_out, int out_size)
{
    const float* x    = (const float*)d_in[0];
    const float* wq   = (const float*)d_in[1];
    const float* wk   = (const float*)d_in[2];
    const float* wv   = (const float*)d_in[3];
    const float* wo   = (const float*)d_in[4];
    const float* bq   = (const float*)d_in[5];
    const float* bk   = (const float*)d_in[6];
    const float* bv   = (const float*)d_in[7];
    const float* bo   = (const float*)d_in[8];
    const float* gq   = (const float*)d_in[9];
    const float* gk   = (const float*)d_in[10];
    const float* fcos = (const float*)d_in[11];
    const float* fsin = (const float*)d_in[12];
    // d_in[13] = seq_lens (all == L)
    const int* pH = (const int*)d_in[15];
    const int* pW = (const int*)d_in[16];
    float* out = (float*)d_out;

    __half *Xh, *Wc, *Woh, *Qh, *Kh, *Vt, *Ah;
    cudaGetSymbolAddress((void**)&Xh, g_Xh);
    cudaGetSymbolAddress((void**)&Wc, g_Wc);
    cudaGetSymbolAddress((void**)&Woh, g_Woh);
    cudaGetSymbolAddress((void**)&Qh, g_Qh);
    cudaGetSymbolAddress((void**)&Kh, g_Kh);
    cudaGetSymbolAddress((void**)&Vt, g_Vt);
    cudaGetSymbolAddress((void**)&Ah, g_Ah);

    cudaFuncSetAttribute(gemm_qkv, cudaFuncAttributeMaxDynamicSharedMemorySize, G_SMEM);
    cudaFuncSetAttribute(gemm_o4, cudaFuncAttributeMaxDynamicSharedMemorySize, O_SMEM);
    cudaFuncSetAttribute(flash_h, cudaFuncAttributeMaxDynamicSharedMemorySize, FL_SMEM);

    const int nX = Lq * Dm, nW = Dm * Dm;
    conv_all<<<dim3(nX / 8 / 256, 5), 256>>>(
        x, wq, wk, wv, wo, Xh,
        Wc, Wc + (size_t)Dm * Dm, Wc + 2 * (size_t)Dm * Dm, Woh, nX, nW);

    gemm_qkv<<<dim3(3 * Dm / 128, Lq / 128), 256, G_SMEM>>>(
        Xh, Wc, bq, bk, bv, Qh, Kh, Vt);

    rmsnorm_rope_h<<<Lq, 256>>>(Qh, Kh, gq, gk, fcos, fsin, pH, pW);

    flash_h<<<dim3(Lq / 128, NH), 256, FL_SMEM>>>(Qh, Kh, Vt, Ah);

    gemm_o4<<<dim3(Dm / 128, Lq / 64), 128, O_SMEM>>>(Ah, Woh, bo, out);
}

// round 16
// speedup vs baseline: 1.0708x; 1.0116x over previous
#include <cuda_runtime.h>
#include <cuda_fp16.h>
#include <math.h>
#include <stdint.h>

// Problem constants (fixed shapes)
#define Lq 4096
#define Dm 1536
#define NH 12
#define HDim 128
#define Cc 64
#define S1c 22
#define S2c 21
#define EPSF 1e-6f

// Scratch (device globals; no runtime allocation allowed)
__device__ __half g_Xh[Lq * Dm];
__device__ __half g_Wc[3 * Dm * Dm];   // Wq | Wk | Wv concatenated along rows
__device__ __half g_Woh[Dm * Dm];
__device__ __half g_Qh[Lq * Dm];
__device__ __half g_Kh[Lq * Dm];
__device__ __half g_Vt[Dm * Lq];       // [d_global][token]
__device__ __half g_Ah[Lq * Dm];

// ---------------------------------------------------------------------------
// Helpers
// ---------------------------------------------------------------------------
__device__ __forceinline__ float ex2f(float x) {
    float y;
    asm("ex2.approx.ftz.f32 %0, %1;" : "=f"(y) : "f"(x));
    return y;
}

__device__ __forceinline__ void mma16(float* c, const uint32_t* a, uint32_t b0, uint32_t b1) {
    asm volatile(
        "mma.sync.aligned.m16n8k16.row.col.f32.f16.f16.f32 "
        "{%0,%1,%2,%3}, {%4,%5,%6,%7}, {%8,%9}, {%0,%1,%2,%3};\n"
        : "+f"(c[0]), "+f"(c[1]), "+f"(c[2]), "+f"(c[3])
        : "r"(a[0]), "r"(a[1]), "r"(a[2]), "r"(a[3]), "r"(b0), "r"(b1));
}

__device__ __forceinline__ void ldsm4(uint32_t& r0, uint32_t& r1, uint32_t& r2,
                                      uint32_t& r3, uint32_t a) {
    asm volatile("ldmatrix.sync.aligned.m8n8.x4.shared.b16 {%0,%1,%2,%3}, [%4];"
                 : "=r"(r0), "=r"(r1), "=r"(r2), "=r"(r3) : "r"(a));
}

__device__ __forceinline__ void cp16(const void* dst_smem, const void* src) {
    uint32_t d = (uint32_t)__cvta_generic_to_shared(dst_smem);
    asm volatile("cp.async.cg.shared.global [%0], [%1], 16;\n" :: "r"(d), "l"(src));
}
#define CP_COMMIT asm volatile("cp.async.commit_group;\n")
#define CP_WAIT(n) asm volatile("cp.async.wait_group %0;\n" :: "n"(n))

__device__ __forceinline__ uint32_t smem_u32(const void* p) {
    return (uint32_t)__cvta_generic_to_shared(p);
}
__device__ __forceinline__ uint32_t ldh2(const __half* p) { return *(const uint32_t*)p; }
__device__ __forceinline__ uint32_t packh2(float a, float b) {
    __half2 h = __floats2half2_rn(a, b);
    return *(uint32_t*)&h;
}

// ---------------------------------------------------------------------------
// fp32 -> fp16 conversion: x + 4 weights in ONE launch (grid.y selects tensor)
// ---------------------------------------------------------------------------
__global__ __launch_bounds__(256) void conv_all(
    const float* __restrict__ x,
    const float* __restrict__ w0, const float* __restrict__ w1,
    const float* __restrict__ w2, const float* __restrict__ w3,
    __half* __restrict__ xo,
    __half* __restrict__ o0, __half* __restrict__ o1,
    __half* __restrict__ o2, __half* __restrict__ o3,
    int nX, int nW)
{
    const float* in; __half* out; int n;
    switch (blockIdx.y) {
        case 0: in = x;  out = xo; n = nX; break;
        case 1: in = w0; out = o0; n = nW; break;
        case 2: in = w1; out = o1; n = nW; break;
        case 3: in = w2; out = o2; n = nW; break;
        default: in = w3; out = o3; n = nW; break;
    }
    int i = (blockIdx.x * 256 + threadIdx.x) * 8;
    if (i < n) {
        float4 v0 = *(const float4*)(in + i);
        float4 v1 = *(const float4*)(in + i + 4);
        uint4 pk;
        pk.x = packh2(v0.x, v0.y); pk.y = packh2(v0.z, v0.w);
        pk.z = packh2(v1.x, v1.y); pk.w = packh2(v1.z, v1.w);
        *(uint4*)(out + i) = pk;
    }
}

// ---------------------------------------------------------------------------
// fp16 GEMM core. mode 0: fp32 row-major out. mode 1: fp16 row-major out.
// mode 2: fp16 TRANSPOSED out to Vt[d][token]. BM=BN=128, BK=32, 8 warps,
// ldmatrix, 5-stage ring (champion schedule: wait; sync; compute; sync; issue).
// ---------------------------------------------------------------------------
#define GSTR 40
#define GTILE (128 * GSTR)
#define GSTAGE (2 * GTILE)
#define NSTG 5
#define G_SMEM (NSTG * GSTAGE * 2)
#define TSTR 136   // transpose-stage stride (halfs)

__device__ __forceinline__ void gemm_body(
    const __half* __restrict__ X, const __half* __restrict__ Wr,
    const float* __restrict__ bias, void* __restrict__ Cout, int mode,
    int m0, int ncol0, __half* smg, __half* __restrict__ VtOut)
{
    const uint32_t sbase = smem_u32(smg);
    const int t = threadIdx.x, lane = t & 31, wid = t >> 5;
    const int g = lane >> 2, t4 = lane & 3;
    const int wm = wid >> 1, wn = wid & 1;

    float acc[2][8][4];
    #pragma unroll
    for (int i = 0; i < 2; i++)
        #pragma unroll
        for (int j = 0; j < 8; j++)
            #pragma unroll
            for (int q = 0; q < 4; q++) acc[i][j][q] = 0.f;

    auto issue = [&](int kt) {
        __half* As = smg + (kt % NSTG) * GSTAGE;
        __half* Bs = As + GTILE;
        const int k0 = kt * 32;
        #pragma unroll
        for (int i = 0; i < 2; i++) {
            int idx = t + i * 256;
            int r = idx >> 2, c = idx & 3;
            cp16(As + r * GSTR + c * 8, X + (size_t)(m0 + r) * Dm + k0 + c * 8);
        }
        #pragma unroll
        for (int i = 0; i < 2; i++) {
            int idx = t + i * 256;
            int r = idx >> 2, c = idx & 3;
            cp16(Bs + r * GSTR + c * 8, Wr + (size_t)r * Dm + k0 + c * 8);
        }
        CP_COMMIT;
    };

    issue(0); issue(1); issue(2); issue(3);

    const uint32_t aOff =
        (uint32_t)(((wm * 32 + (lane & 7) + ((lane >> 3) & 1) * 8) * GSTR +
                    (lane >> 4) * 8) * 2);
    const uint32_t bOff =
        (uint32_t)(((wn * 64 + (lane & 7) + (lane >> 4) * 8) * GSTR +
                    ((lane >> 3) & 1) * 8) * 2);

    const int KT = Dm / 32;
    for (int kt = 0; kt < KT; kt++) {
        // exact outstanding-group wait: guarantee stage kt complete
        if (kt < KT - 3)       CP_WAIT(3);
        else if (kt == KT - 3) CP_WAIT(2);
        else if (kt == KT - 2) CP_WAIT(1);
        else                   CP_WAIT(0);
        __syncthreads();
        const uint32_t stA = sbase + (uint32_t)((kt % NSTG) * GSTAGE * 2);
        const uint32_t stB = stA + GTILE * 2;
        #pragma unroll
        for (int ks = 0; ks < 2; ks++) {
            uint32_t af[2][4], bf[8][2];
            ldsm4(af[0][0], af[0][1], af[0][2], af[0][3], stA + aOff + ks * 32);
            ldsm4(af[1][0], af[1][1], af[1][2], af[1][3],
                  stA + aOff + 16 * GSTR * 2 + ks * 32);
            #pragma unroll
            for (int jj = 0; jj < 4; jj++)
                ldsm4(bf[2 * jj][0], bf[2 * jj][1], bf[2 * jj + 1][0], bf[2 * jj + 1][1],
                      stB + bOff + jj * 16 * GSTR * 2 + ks * 32);
            #pragma unroll
            for (int i = 0; i < 2; i++)
                #pragma unroll
                for (int j = 0; j < 8; j++)
                    mma16(acc[i][j], af[i], bf[j][0], bf[j][1]);
        }
        __syncthreads();
        if (kt + 4 < KT) issue(kt + 4);
    }

    if (mode == 2) {
        __syncthreads();
        __half* Ts = smg;
        #pragma unroll
        for (int j = 0; j < 8; j++) {
            int lc = wn * 64 + j * 8 + 2 * t4;
            float b0 = bias[lc], b1 = bias[lc + 1];
            #pragma unroll
            for (int i = 0; i < 2; i++) {
                int r = wm * 32 + i * 16 + g;
                Ts[lc * TSTR + r]           = __float2half_rn(acc[i][j][0] + b0);
                Ts[(lc + 1) * TSTR + r]     = __float2half_rn(acc[i][j][1] + b1);
                Ts[lc * TSTR + r + 8]       = __float2half_rn(acc[i][j][2] + b0);
                Ts[(lc + 1) * TSTR + r + 8] = __float2half_rn(acc[i][j][3] + b1);
            }
        }
        __syncthreads();
        #pragma unroll
        for (int i = 0; i < 8; i++) {
            int idx = t + i * 256;
            int c = idx >> 4, ch = idx & 15;
            *(uint4*)(VtOut + (size_t)(ncol0 + c) * Lq + m0 + ch * 8) =
                *(const uint4*)(Ts + c * TSTR + ch * 8);
        }
        return;
    }

    #pragma unroll
    for (int j = 0; j < 8; j++) {
        int lc = wn * 64 + j * 8 + 2 * t4;
        float b0 = bias[lc], b1 = bias[lc + 1];
        int col = ncol0 + lc;
        #pragma unroll
        for (int i = 0; i < 2; i++) {
            int row = m0 + wm * 32 + i * 16 + g;
            float c00 = acc[i][j][0] + b0, c01 = acc[i][j][1] + b1;
            float c10 = acc[i][j][2] + b0, c11 = acc[i][j][3] + b1;
            if (mode == 1) {
                __half* C = (__half*)Cout;
                *(__half2*)(C + (size_t)row * Dm + col) = __floats2half2_rn(c00, c01);
                *(__half2*)(C + (size_t)(row + 8) * Dm + col) = __floats2half2_rn(c10, c11);
            } else {
                float* C = (float*)Cout;
                *(float2*)(C + (size_t)row * Dm + col) = make_float2(c00, c01);
                *(float2*)(C + (size_t)(row + 8) * Dm + col) = make_float2(c10, c11);
            }
        }
    }
}

// Fused QKV: grid (3*Dm/128, Lq/128). V segment written transposed to Vt.
__global__ __launch_bounds__(256, 2) void gemm_qkv(
    const __half* __restrict__ X, const __half* __restrict__ Wc,
    const float* __restrict__ bq, const float* __restrict__ bk,
    const float* __restrict__ bv,
    __half* __restrict__ Qh, __half* __restrict__ Kh, __half* __restrict__ Vt)
{
    extern __shared__ __half smg[];
    const int n0g = blockIdx.x * 128;
    const int seg = n0g / Dm;
    const int n0 = n0g - seg * Dm;
    const float* bias = (seg == 0) ? bq : (seg == 1) ? bk : bv;
    if (seg < 2) {
        gemm_body(X, Wc + (size_t)n0g * Dm, bias + n0, seg ? Kh : Qh, 1,
                  blockIdx.y * 128, n0, smg, nullptr);
    } else {
        gemm_body(X, Wc + (size_t)n0g * Dm, bias + n0, nullptr, 2,
                  blockIdx.y * 128, n0, smg, Vt);
    }
}

// Output projection (fp32 out) — champion config (BM=128)
__global__ __launch_bounds__(256, 2) void gemm_o(
    const __half* __restrict__ X, const __half* __restrict__ W,
    const float* __restrict__ bias, float* __restrict__ out)
{
    extern __shared__ __half smg[];
    const int n0 = blockIdx.x * 128;
    gemm_body(X, W + (size_t)n0 * Dm, bias + n0, out, 0, blockIdx.y * 128, n0,
              smg, nullptr);
}

// ---------------------------------------------------------------------------
// Single-pass RMSNorm + 3D RoPE; ONE block handles BOTH the Q row and K row.
// ---------------------------------------------------------------------------
__global__ __launch_bounds__(256) void rmsnorm_rope_h(
    __half* __restrict__ Tq, __half* __restrict__ Tk,
    const float* __restrict__ gqv, const float* __restrict__ gkv,
    const float* __restrict__ fcos, const float* __restrict__ fsin,
    const int* __restrict__ pH, const int* __restrict__ pW)
{
    const int row = blockIdx.x;
    const int tid = threadIdx.x;
    const int lane = tid & 31, wid = tid >> 5;
    __shared__ float red[8];

    const int H = *pH, W = *pW;
    const int f = row / (H * W);
    const int hh = (row / W) % H;
    const int ww = row % W;

    float cc[3], ssn[3];
    #pragma unroll
    for (int k = 0; k < 3; k++) {
        int pj = tid + k * 256;
        int j = pj & 63;
        const int coord = (j < S1c) ? f : ((j < S1c + S2c) ? hh : ww);
        cc[k]  = fcos[coord * Cc + j];
        ssn[k] = fsin[coord * Cc + j];
    }

    #pragma unroll
    for (int which = 0; which < 2; which++) {
        __half* p = (which ? Tk : Tq) + (size_t)row * Dm;
        const float* g = which ? gkv : gqv;

        float2 vf[3];
        float ss = 0.f;
        #pragma unroll
        for (int k = 0; k < 3; k++) {
            int pj = tid + k * 256;
            vf[k] = __half22float2(*(const __half2*)(p + 2 * pj));
            ss += vf[k].x * vf[k].x + vf[k].y * vf[k].y;
        }
        #pragma unroll
        for (int off = 16; off >= 1; off >>= 1)
            ss += __shfl_xor_sync(0xffffffffu, ss, off);
        if (lane == 0) red[wid] = ss;
        __syncthreads();
        if (wid == 0) {
            float v = (lane < 8) ? red[lane] : 0.f;
            #pragma unroll
            for (int off = 4; off >= 1; off >>= 1)
                v += __shfl_xor_sync(0xffffffffu, v, off);
            if (lane == 0) red[0] = rsqrtf(v * (1.f / Dm) + EPSF);
        }
        __syncthreads();
        const float rms = red[0];
        __syncthreads();   // protect red[] reuse by second tensor

        #pragma unroll
        for (int k = 0; k < 3; k++) {
            int pj = tid + k * 256;
            float2 gg = *(const float2*)(g + 2 * pj);
            const float xr = vf[k].x * rms * gg.x;
            const float xi = vf[k].y * rms * gg.y;
            *(__half2*)(p + 2 * pj) = __floats2half2_rn(xr * cc[k] - xi * ssn[k],
                                                        xr * ssn[k] + xi * cc[k]);
        }
    }
}

// ---------------------------------------------------------------------------
// Flash attention — champion config, at the fp16 mma.sync ceiling.
// BQ=128, key tile 64, 256 threads, P in registers, 4-stage ring, depth 2,
// one barrier/iter, issue-before-wait.
// ---------------------------------------------------------------------------
#define KSTR 136
#define VSTR 72
#define FNST 4
#define FL_SMEM ((FNST * 64 * KSTR + FNST * 128 * VSTR) * 2)

__global__ __launch_bounds__(256, 1) void flash_h(
    const __half* __restrict__ Q, const __half* __restrict__ K,
    const __half* __restrict__ Vt, __half* __restrict__ O)
{
    extern __shared__ __half smf[];
    __half* Ks = smf;
    __half* Vs = Ks + FNST * 64 * KSTR;
    const uint32_t sB = smem_u32(smf);

    const int t = threadIdx.x, lane = t & 31, wid = t >> 5;
    const int g = lane >> 2, t4 = lane & 3;
    const int head = blockIdx.y;
    const int q0 = blockIdx.x * 128;
    const __half* Qg = Q + (size_t)q0 * Dm + head * HDim;
    const __half* Kg0 = K + head * HDim;
    const __half* Vtg = Vt + (size_t)(head * HDim) * Lq;

    for (int i = t; i < 128 * 16; i += 256) {
        int r = i >> 4, c = i & 15;
        *(uint4*)(Ks + r * KSTR + c * 8) = *(const uint4*)(Qg + (size_t)r * Dm + c * 8);
    }
    __syncthreads();
    uint32_t qf[8][4];
    {
        const __half* bp = Ks + (wid * 16 + g) * KSTR;
        #pragma unroll
        for (int ks = 0; ks < 8; ks++) {
            qf[ks][0] = ldh2(bp + ks * 16 + 2 * t4);
            qf[ks][1] = ldh2(bp + 8 * KSTR + ks * 16 + 2 * t4);
            qf[ks][2] = ldh2(bp + ks * 16 + 2 * t4 + 8);
            qf[ks][3] = ldh2(bp + 8 * KSTR + ks * 16 + 2 * t4 + 8);
        }
    }
    __syncthreads();

    float o[16][4];
    #pragma unroll
    for (int j = 0; j < 16; j++) { o[j][0] = o[j][1] = o[j][2] = o[j][3] = 0.f; }
    float m0 = -1e30f, m1 = -1e30f, l0 = 0.f, l1 = 0.f;
    const float KS2 = 0.08838834764831845f * 1.4426950408889634f;

    auto issue = [&](int kt) {
        const int b = kt & (FNST - 1);
        const __half* Kg = Kg0 + (size_t)(kt * 64) * Dm;
        __half* Kd = Ks + b * 64 * KSTR;
        __half* Vd = Vs + b * 128 * VSTR;
        #pragma unroll
        for (int i = 0; i < 4; i++) {
            int idx = t + i * 256;
            int r = idx >> 4, c = idx & 15;
            cp16(Kd + r * KSTR + c * 8, Kg + (size_t)r * Dm + c * 8);
        }
        #pragma unroll
        for (int i = 0; i < 4; i++) {
            int idx = t + i * 256;
            int r = idx >> 3, c = idx & 7;
            cp16(Vd + r * VSTR + c * 8, Vtg + (size_t)r * Lq + kt * 64 + c * 8);
        }
        CP_COMMIT;
    };

    const uint32_t kOff =
        (uint32_t)((((lane & 7) + (lane >> 4) * 8) * KSTR + ((lane >> 3) & 1) * 8) * 2);
    const uint32_t vOff =
        (uint32_t)((((lane & 7) + (lane >> 4) * 8) * VSTR + ((lane >> 3) & 1) * 8) * 2);

    issue(0); issue(1);
    const int NT = Lq / 64;
    for (int kt = 0; kt < NT; kt++) {
        const int b = kt & (FNST - 1);
        if (kt + 2 < NT) { issue(kt + 2); CP_WAIT(2); }
        else if (kt + 1 < NT) { CP_WAIT(1); }
        else { CP_WAIT(0); }
        __syncthreads();   // stage b visible; writer stage (kt+2)%4 is 3 away from slowest reader

        const uint32_t stK = sB + (uint32_t)(b * 64 * KSTR * 2);
        const uint32_t stV = sB + (uint32_t)((FNST * 64 * KSTR + b * 128 * VSTR) * 2);

        float s[8][4];
        #pragma unroll
        for (int j = 0; j < 8; j++) { s[j][0] = s[j][1] = s[j][2] = s[j][3] = 0.f; }
        #pragma unroll
        for (int ks = 0; ks < 8; ks++) {
            uint32_t kf[8][2];
            #pragma unroll
            for (int jj = 0; jj < 4; jj++)
                ldsm4(kf[2 * jj][0], kf[2 * jj][1], kf[2 * jj + 1][0], kf[2 * jj + 1][1],
                      stK + kOff + jj * 16 * KSTR * 2 + ks * 32);
            #pragma unroll
            for (int j = 0; j < 8; j++)
                mma16(s[j], qf[ks], kf[j][0], kf[j][1]);
        }

        float mx0 = -1e30f, mx1 = -1e30f;
        #pragma unroll
        for (int j = 0; j < 8; j++) {
            mx0 = fmaxf(mx0, fmaxf(s[j][0], s[j][1]));
            mx1 = fmaxf(mx1, fmaxf(s[j][2], s[j][3]));
        }
        mx0 *= KS2; mx1 *= KS2;
        mx0 = fmaxf(mx0, __shfl_xor_sync(0xffffffffu, mx0, 1));
        mx0 = fmaxf(mx0, __shfl_xor_sync(0xffffffffu, mx0, 2));
        mx1 = fmaxf(mx1, __shfl_xor_sync(0xffffffffu, mx1, 1));
        mx1 = fmaxf(mx1, __shfl_xor_sync(0xffffffffu, mx1, 2));
        float nm0 = fmaxf(m0, mx0), nm1 = fmaxf(m1, mx1);
        float corr0 = ex2f(m0 - nm0), corr1 = ex2f(m1 - nm1);
        m0 = nm0; m1 = nm1;
        float r0 = 0.f, r1 = 0.f;
        uint32_t ph[8][2];
        #pragma unroll
        for (int j = 0; j < 8; j++) {
            float p00 = ex2f(s[j][0] * KS2 - m0);
            float p01 = ex2f(s[j][1] * KS2 - m0);
            float p10 = ex2f(s[j][2] * KS2 - m1);
            float p11 = ex2f(s[j][3] * KS2 - m1);
            r0 += p00 + p01; r1 += p10 + p11;
            ph[j][0] = packh2(p00, p01);
            ph[j][1] = packh2(p10, p11);
        }
        r0 += __shfl_xor_sync(0xffffffffu, r0, 1);
        r0 += __shfl_xor_sync(0xffffffffu, r0, 2);
        r1 += __shfl_xor_sync(0xffffffffu, r1, 1);
        r1 += __shfl_xor_sync(0xffffffffu, r1, 2);
        l0 = l0 * corr0 + r0;
        l1 = l1 * corr1 + r1;
        #pragma unroll
        for (int j = 0; j < 16; j++) {
            o[j][0] *= corr0; o[j][1] *= corr0;
            o[j][2] *= corr1; o[j][3] *= corr1;
        }

        #pragma unroll
        for (int mm = 0; mm < 4; mm++) {
            uint32_t a[4] = { ph[2 * mm][0], ph[2 * mm][1],
                              ph[2 * mm + 1][0], ph[2 * mm + 1][1] };
            #pragma unroll
            for (int jj = 0; jj < 8; jj++) {
                uint32_t v0, v1, v2, v3;
                ldsm4(v0, v1, v2, v3, stV + vOff + jj * 16 * VSTR * 2 + mm * 32);
                mma16(o[2 * jj], a, v0, v1);
                mma16(o[2 * jj + 1], a, v2, v3);
            }
        }
    }

    const float inv0 = 1.f / l0, inv1 = 1.f / l1;
    __half* O0 = O + (size_t)(q0 + wid * 16 + g) * Dm + head * HDim + 2 * t4;
    __half* O1 = O0 + 8 * (size_t)Dm;
    #pragma unroll
    for (int j = 0; j < 16; j++) {
        *(__half2*)(O0 + j * 8) = __floats2half2_rn(o[j][0] * inv0, o[j][1] * inv0);
        *(__half2*)(O1 + j * 8) = __floats2half2_rn(o[j][2] * inv1, o[j][3] * inv1);
    }
}

// ---------------------------------------------------------------------------
// Launch
// ---------------------------------------------------------------------------
extern "C" void kernel_launch(void* const* d_in, const int* in_sizes, int n_in,
                              void* d_out, int out_size)
{
    const float* x    = (const float*)d_in[0];
    const float* wq   = (const float*)d_in[1];
    const float* wk   = (const float*)d_in[2];
    const float* wv   = (const float*)d_in[3];
    const float* wo   = (const float*)d_in[4];
    const float* bq   = (const float*)d_in[5];
    const float* bk   = (const float*)d_in[6];
    const float* bv   = (const float*)d_in[7];
    const float* bo   = (const float*)d_in[8];
    const float* gq   = (const float*)d_in[9];
    const float* gk   = (const float*)d_in[10];
    const float* fcos = (const float*)d_in[11];
    const float* fsin = (const float*)d_in[12];
    // d_in[13] = seq_lens (all == L)
    const int* pH = (const int*)d_in[15];
    const int* pW = (const int*)d_in[16];
    float* out = (float*)d_out;

    __half *Xh, *Wc, *Woh, *Qh, *Kh, *Vt, *Ah;
    cudaGetSymbolAddress((void**)&Xh, g_Xh);
    cudaGetSymbolAddress((void**)&Wc, g_Wc);
    cudaGetSymbolAddress((void**)&Woh, g_Woh);
    cudaGetSymbolAddress((void**)&Qh, g_Qh);
    cudaGetSymbolAddress((void**)&Kh, g_Kh);
    cudaGetSymbolAddress((void**)&Vt, g_Vt);
    cudaGetSymbolAddress((void**)&Ah, g_Ah);

    cudaFuncSetAttribute(gemm_qkv, cudaFuncAttributeMaxDynamicSharedMemorySize, G_SMEM);
    cudaFuncSetAttribute(gemm_o, cudaFuncAttributeMaxDynamicSharedMemorySize, G_SMEM);
    cudaFuncSetAttribute(flash_h, cudaFuncAttributeMaxDynamicSharedMemorySize, FL_SMEM);

    const int nX = Lq * Dm, nW = Dm * Dm;
    conv_all<<<dim3(nX / 8 / 256, 5), 256>>>(
        x, wq, wk, wv, wo, Xh,
        Wc, Wc + (size_t)Dm * Dm, Wc + 2 * (size_t)Dm * Dm, Woh, nX, nW);

    gemm_qkv<<<dim3(3 * Dm / 128, Lq / 128), 256, G_SMEM>>>(
        Xh, Wc, bq, bk, bv, Qh, Kh, Vt);

    rmsnorm_rope_h<<<Lq, 256>>>(Qh, Kh, gq, gk, fcos, fsin, pH, pW);

    flash_h<<<dim3(Lq / 128, NH), 256, FL_SMEM>>>(Qh, Kh, Vt, Ah);

    gemm_o<<<dim3(Dm / 128, Lq / 128), 256, G_SMEM>>>(Ah, Woh, bo, out);
}

// round 17
// speedup vs baseline: 1.0779x; 1.0066x over previous
#include <cuda_runtime.h>
#include <cuda_fp16.h>
#include <math.h>
#include <stdint.h>

// Problem constants (fixed shapes)
#define Lq 4096
#define Dm 1536
#define NH 12
#define HDim 128
#define Cc 64
#define S1c 22
#define S2c 21
#define EPSF 1e-6f

// Scratch (device globals; no runtime allocation allowed)
__device__ __half g_Xh[Lq * Dm];
__device__ __half g_Wc[3 * Dm * Dm];   // Wq | Wk | Wv concatenated along rows
__device__ __half g_Woh[Dm * Dm];
__device__ __half g_Qh[Lq * Dm];
__device__ __half g_Kh[Lq * Dm];
__device__ __half g_Vt[Dm * Lq];       // [d_global][token]
__device__ __half g_Ah[Lq * Dm];

// ---------------------------------------------------------------------------
// Helpers
// ---------------------------------------------------------------------------
__device__ __forceinline__ float ex2f(float x) {
    float y;
    asm("ex2.approx.ftz.f32 %0, %1;" : "=f"(y) : "f"(x));
    return y;
}

__device__ __forceinline__ void mma16(float* c, const uint32_t* a, uint32_t b0, uint32_t b1) {
    asm volatile(
        "mma.sync.aligned.m16n8k16.row.col.f32.f16.f16.f32 "
        "{%0,%1,%2,%3}, {%4,%5,%6,%7}, {%8,%9}, {%0,%1,%2,%3};\n"
        : "+f"(c[0]), "+f"(c[1]), "+f"(c[2]), "+f"(c[3])
        : "r"(a[0]), "r"(a[1]), "r"(a[2]), "r"(a[3]), "r"(b0), "r"(b1));
}

__device__ __forceinline__ void ldsm4(uint32_t& r0, uint32_t& r1, uint32_t& r2,
                                      uint32_t& r3, uint32_t a) {
    asm volatile("ldmatrix.sync.aligned.m8n8.x4.shared.b16 {%0,%1,%2,%3}, [%4];"
                 : "=r"(r0), "=r"(r1), "=r"(r2), "=r"(r3) : "r"(a));
}

__device__ __forceinline__ void cp16(const void* dst_smem, const void* src) {
    uint32_t d = (uint32_t)__cvta_generic_to_shared(dst_smem);
    asm volatile("cp.async.cg.shared.global [%0], [%1], 16;\n" :: "r"(d), "l"(src));
}
#define CP_COMMIT asm volatile("cp.async.commit_group;\n")
#define CP_WAIT(n) asm volatile("cp.async.wait_group %0;\n" :: "n"(n))

__device__ __forceinline__ uint32_t smem_u32(const void* p) {
    return (uint32_t)__cvta_generic_to_shared(p);
}
__device__ __forceinline__ uint32_t ldh2(const __half* p) { return *(const uint32_t*)p; }
__device__ __forceinline__ uint32_t packh2(float a, float b) {
    __half2 h = __floats2half2_rn(a, b);
    return *(uint32_t*)&h;
}

// ---------------------------------------------------------------------------
// fp32 -> fp16 conversion: x + 4 weights in ONE launch (grid.y selects tensor)
// ---------------------------------------------------------------------------
__global__ __launch_bounds__(256) void conv_all(
    const float* __restrict__ x,
    const float* __restrict__ w0, const float* __restrict__ w1,
    const float* __restrict__ w2, const float* __restrict__ w3,
    __half* __restrict__ xo,
    __half* __restrict__ o0, __half* __restrict__ o1,
    __half* __restrict__ o2, __half* __restrict__ o3,
    int nX, int nW)
{
    const float* in; __half* out; int n;
    switch (blockIdx.y) {
        case 0: in = x;  out = xo; n = nX; break;
        case 1: in = w0; out = o0; n = nW; break;
        case 2: in = w1; out = o1; n = nW; break;
        case 3: in = w2; out = o2; n = nW; break;
        default: in = w3; out = o3; n = nW; break;
    }
    int i = (blockIdx.x * 256 + threadIdx.x) * 8;
    if (i < n) {
        float4 v0 = *(const float4*)(in + i);
        float4 v1 = *(const float4*)(in + i + 4);
        uint4 pk;
        pk.x = packh2(v0.x, v0.y); pk.y = packh2(v0.z, v0.w);
        pk.z = packh2(v1.x, v1.y); pk.w = packh2(v1.z, v1.w);
        *(uint4*)(out + i) = pk;
    }
}

// ---------------------------------------------------------------------------
// fp16 GEMM core. mode 0: fp32 row-major out. mode 1: fp16 row-major out.
// mode 2: fp16 TRANSPOSED out to Vt[d][token]. BM=BN=128, BK=32, 8 warps,
// ldmatrix, 5-stage ring, SINGLE barrier per K-tile:
//   wait(exact) -> barrier -> issue(kt+4) -> compute.
// Writer stage (kt+4)%5 != reader stage kt%5; its previous readers (iter
// kt-1) are fenced by the barrier just crossed.
// ---------------------------------------------------------------------------
#define GSTR 40
#define GTILE (128 * GSTR)
#define GSTAGE (2 * GTILE)
#define NSTG 5
#define G_SMEM (NSTG * GSTAGE * 2)
#define TSTR 136   // transpose-stage stride (halfs)

__device__ __forceinline__ void gemm_body(
    const __half* __restrict__ X, const __half* __restrict__ Wr,
    const float* __restrict__ bias, void* __restrict__ Cout, int mode,
    int m0, int ncol0, __half* smg, __half* __restrict__ VtOut)
{
    const uint32_t sbase = smem_u32(smg);
    const int t = threadIdx.x, lane = t & 31, wid = t >> 5;
    const int g = lane >> 2, t4 = lane & 3;
    const int wm = wid >> 1, wn = wid & 1;

    float acc[2][8][4];
    #pragma unroll
    for (int i = 0; i < 2; i++)
        #pragma unroll
        for (int j = 0; j < 8; j++)
            #pragma unroll
            for (int q = 0; q < 4; q++) acc[i][j][q] = 0.f;

    auto issue = [&](int kt) {
        __half* As = smg + (kt % NSTG) * GSTAGE;
        __half* Bs = As + GTILE;
        const int k0 = kt * 32;
        #pragma unroll
        for (int i = 0; i < 2; i++) {
            int idx = t + i * 256;
            int r = idx >> 2, c = idx & 3;
            cp16(As + r * GSTR + c * 8, X + (size_t)(m0 + r) * Dm + k0 + c * 8);
        }
        #pragma unroll
        for (int i = 0; i < 2; i++) {
            int idx = t + i * 256;
            int r = idx >> 2, c = idx & 3;
            cp16(Bs + r * GSTR + c * 8, Wr + (size_t)r * Dm + k0 + c * 8);
        }
        CP_COMMIT;
    };

    issue(0); issue(1); issue(2); issue(3);

    const uint32_t aOff =
        (uint32_t)(((wm * 32 + (lane & 7) + ((lane >> 3) & 1) * 8) * GSTR +
                    (lane >> 4) * 8) * 2);
    const uint32_t bOff =
        (uint32_t)(((wn * 64 + (lane & 7) + (lane >> 4) * 8) * GSTR +
                    ((lane >> 3) & 1) * 8) * 2);

    const int KT = Dm / 32;
    for (int kt = 0; kt < KT; kt++) {
        // exact outstanding-group wait: guarantee stage kt complete
        if (kt < KT - 3)       CP_WAIT(3);
        else if (kt == KT - 3) CP_WAIT(2);
        else if (kt == KT - 2) CP_WAIT(1);
        else                   CP_WAIT(0);
        __syncthreads();
        if (kt + 4 < KT) issue(kt + 4);   // single-barrier schedule (R9 GEMM win)

        const uint32_t stA = sbase + (uint32_t)((kt % NSTG) * GSTAGE * 2);
        const uint32_t stB = stA + GTILE * 2;
        #pragma unroll
        for (int ks = 0; ks < 2; ks++) {
            uint32_t af[2][4], bf[8][2];
            ldsm4(af[0][0], af[0][1], af[0][2], af[0][3], stA + aOff + ks * 32);
            ldsm4(af[1][0], af[1][1], af[1][2], af[1][3],
                  stA + aOff + 16 * GSTR * 2 + ks * 32);
            #pragma unroll
            for (int jj = 0; jj < 4; jj++)
                ldsm4(bf[2 * jj][0], bf[2 * jj][1], bf[2 * jj + 1][0], bf[2 * jj + 1][1],
                      stB + bOff + jj * 16 * GSTR * 2 + ks * 32);
            #pragma unroll
            for (int i = 0; i < 2; i++)
                #pragma unroll
                for (int j = 0; j < 8; j++)
                    mma16(acc[i][j], af[i], bf[j][0], bf[j][1]);
        }
    }

    if (mode == 2) {
        __syncthreads();
        __half* Ts = smg;
        #pragma unroll
        for (int j = 0; j < 8; j++) {
            int lc = wn * 64 + j * 8 + 2 * t4;
            float b0 = bias[lc], b1 = bias[lc + 1];
            #pragma unroll
            for (int i = 0; i < 2; i++) {
                int r = wm * 32 + i * 16 + g;
                Ts[lc * TSTR + r]           = __float2half_rn(acc[i][j][0] + b0);
                Ts[(lc + 1) * TSTR + r]     = __float2half_rn(acc[i][j][1] + b1);
                Ts[lc * TSTR + r + 8]       = __float2half_rn(acc[i][j][2] + b0);
                Ts[(lc + 1) * TSTR + r + 8] = __float2half_rn(acc[i][j][3] + b1);
            }
        }
        __syncthreads();
        #pragma unroll
        for (int i = 0; i < 8; i++) {
            int idx = t + i * 256;
            int c = idx >> 4, ch = idx & 15;
            *(uint4*)(VtOut + (size_t)(ncol0 + c) * Lq + m0 + ch * 8) =
                *(const uint4*)(Ts + c * TSTR + ch * 8);
        }
        return;
    }

    #pragma unroll
    for (int j = 0; j < 8; j++) {
        int lc = wn * 64 + j * 8 + 2 * t4;
        float b0 = bias[lc], b1 = bias[lc + 1];
        int col = ncol0 + lc;
        #pragma unroll
        for (int i = 0; i < 2; i++) {
            int row = m0 + wm * 32 + i * 16 + g;
            float c00 = acc[i][j][0] + b0, c01 = acc[i][j][1] + b1;
            float c10 = acc[i][j][2] + b0, c11 = acc[i][j][3] + b1;
            if (mode == 1) {
                __half* C = (__half*)Cout;
                *(__half2*)(C + (size_t)row * Dm + col) = __floats2half2_rn(c00, c01);
                *(__half2*)(C + (size_t)(row + 8) * Dm + col) = __floats2half2_rn(c10, c11);
            } else {
                float* C = (float*)Cout;
                *(float2*)(C + (size_t)row * Dm + col) = make_float2(c00, c01);
                *(float2*)(C + (size_t)(row + 8) * Dm + col) = make_float2(c10, c11);
            }
        }
    }
}

// Fused QKV: grid (3*Dm/128, Lq/128). V segment written transposed to Vt.
__global__ __launch_bounds__(256, 2) void gemm_qkv(
    const __half* __restrict__ X, const __half* __restrict__ Wc,
    const float* __restrict__ bq, const float* __restrict__ bk,
    const float* __restrict__ bv,
    __half* __restrict__ Qh, __half* __restrict__ Kh, __half* __restrict__ Vt)
{
    extern __shared__ __half smg[];
    const int n0g = blockIdx.x * 128;
    const int seg = n0g / Dm;
    const int n0 = n0g - seg * Dm;
    const float* bias = (seg == 0) ? bq : (seg == 1) ? bk : bv;
    if (seg < 2) {
        gemm_body(X, Wc + (size_t)n0g * Dm, bias + n0, seg ? Kh : Qh, 1,
                  blockIdx.y * 128, n0, smg, nullptr);
    } else {
        gemm_body(X, Wc + (size_t)n0g * Dm, bias + n0, nullptr, 2,
                  blockIdx.y * 128, n0, smg, Vt);
    }
}

// Output projection (fp32 out) — BM=128
__global__ __launch_bounds__(256, 2) void gemm_o(
    const __half* __restrict__ X, const __half* __restrict__ W,
    const float* __restrict__ bias, float* __restrict__ out)
{
    extern __shared__ __half smg[];
    const int n0 = blockIdx.x * 128;
    gemm_body(X, W + (size_t)n0 * Dm, bias + n0, out, 0, blockIdx.y * 128, n0,
              smg, nullptr);
}

// ---------------------------------------------------------------------------
// Single-pass RMSNorm + 3D RoPE; ONE block handles BOTH the Q row and K row.
// ---------------------------------------------------------------------------
__global__ __launch_bounds__(256) void rmsnorm_rope_h(
    __half* __restrict__ Tq, __half* __restrict__ Tk,
    const float* __restrict__ gqv, const float* __restrict__ gkv,
    const float* __restrict__ fcos, const float* __restrict__ fsin,
    const int* __restrict__ pH, const int* __restrict__ pW)
{
    const int row = blockIdx.x;
    const int tid = threadIdx.x;
    const int lane = tid & 31, wid = tid >> 5;
    __shared__ float red[8];

    const int H = *pH, W = *pW;
    const int f = row / (H * W);
    const int hh = (row / W) % H;
    const int ww = row % W;

    float cc[3], ssn[3];
    #pragma unroll
    for (int k = 0; k < 3; k++) {
        int pj = tid + k * 256;
        int j = pj & 63;
        const int coord = (j < S1c) ? f : ((j < S1c + S2c) ? hh : ww);
        cc[k]  = fcos[coord * Cc + j];
        ssn[k] = fsin[coord * Cc + j];
    }

    #pragma unroll
    for (int which = 0; which < 2; which++) {
        __half* p = (which ? Tk : Tq) + (size_t)row * Dm;
        const float* g = which ? gkv : gqv;

        float2 vf[3];
        float ss = 0.f;
        #pragma unroll
        for (int k = 0; k < 3; k++) {
            int pj = tid + k * 256;
            vf[k] = __half22float2(*(const __half2*)(p + 2 * pj));
            ss += vf[k].x * vf[k].x + vf[k].y * vf[k].y;
        }
        #pragma unroll
        for (int off = 16; off >= 1; off >>= 1)
            ss += __shfl_xor_sync(0xffffffffu, ss, off);
        if (lane == 0) red[wid] = ss;
        __syncthreads();
        if (wid == 0) {
            float v = (lane < 8) ? red[lane] : 0.f;
            #pragma unroll
            for (int off = 4; off >= 1; off >>= 1)
                v += __shfl_xor_sync(0xffffffffu, v, off);
            if (lane == 0) red[0] = rsqrtf(v * (1.f / Dm) + EPSF);
        }
        __syncthreads();
        const float rms = red[0];
        __syncthreads();   // protect red[] reuse by second tensor

        #pragma unroll
        for (int k = 0; k < 3; k++) {
            int pj = tid + k * 256;
            float2 gg = *(const float2*)(g + 2 * pj);
            const float xr = vf[k].x * rms * gg.x;
            const float xi = vf[k].y * rms * gg.y;
            *(__half2*)(p + 2 * pj) = __floats2half2_rn(xr * cc[k] - xi * ssn[k],
                                                        xr * ssn[k] + xi * cc[k]);
        }
    }
}

// ---------------------------------------------------------------------------
// Flash attention — champion config, FROZEN (at the fp16 mma.sync ceiling).
// ---------------------------------------------------------------------------
#define KSTR 136
#define VSTR 72
#define FNST 4
#define FL_SMEM ((FNST * 64 * KSTR + FNST * 128 * VSTR) * 2)

__global__ __launch_bounds__(256, 1) void flash_h(
    const __half* __restrict__ Q, const __half* __restrict__ K,
    const __half* __restrict__ Vt, __half* __restrict__ O)
{
    extern __shared__ __half smf[];
    __half* Ks = smf;
    __half* Vs = Ks + FNST * 64 * KSTR;
    const uint32_t sB = smem_u32(smf);

    const int t = threadIdx.x, lane = t & 31, wid = t >> 5;
    const int g = lane >> 2, t4 = lane & 3;
    const int head = blockIdx.y;
    const int q0 = blockIdx.x * 128;
    const __half* Qg = Q + (size_t)q0 * Dm + head * HDim;
    const __half* Kg0 = K + head * HDim;
    const __half* Vtg = Vt + (size_t)(head * HDim) * Lq;

    for (int i = t; i < 128 * 16; i += 256) {
        int r = i >> 4, c = i & 15;
        *(uint4*)(Ks + r * KSTR + c * 8) = *(const uint4*)(Qg + (size_t)r * Dm + c * 8);
    }
    __syncthreads();
    uint32_t qf[8][4];
    {
        const __half* bp = Ks + (wid * 16 + g) * KSTR;
        #pragma unroll
        for (int ks = 0; ks < 8; ks++) {
            qf[ks][0] = ldh2(bp + ks * 16 + 2 * t4);
            qf[ks][1] = ldh2(bp + 8 * KSTR + ks * 16 + 2 * t4);
            qf[ks][2] = ldh2(bp + ks * 16 + 2 * t4 + 8);
            qf[ks][3] = ldh2(bp + 8 * KSTR + ks * 16 + 2 * t4 + 8);
        }
    }
    __syncthreads();

    float o[16][4];
    #pragma unroll
    for (int j = 0; j < 16; j++) { o[j][0] = o[j][1] = o[j][2] = o[j][3] = 0.f; }
    float m0 = -1e30f, m1 = -1e30f, l0 = 0.f, l1 = 0.f;
    const float KS2 = 0.08838834764831845f * 1.4426950408889634f;

    auto issue = [&](int kt) {
        const int b = kt & (FNST - 1);
        const __half* Kg = Kg0 + (size_t)(kt * 64) * Dm;
        __half* Kd = Ks + b * 64 * KSTR;
        __half* Vd = Vs + b * 128 * VSTR;
        #pragma unroll
        for (int i = 0; i < 4; i++) {
            int idx = t + i * 256;
            int r = idx >> 4, c = idx & 15;
            cp16(Kd + r * KSTR + c * 8, Kg + (size_t)r * Dm + c * 8);
        }
        #pragma unroll
        for (int i = 0; i < 4; i++) {
            int idx = t + i * 256;
            int r = idx >> 3, c = idx & 7;
            cp16(Vd + r * VSTR + c * 8, Vtg + (size_t)r * Lq + kt * 64 + c * 8);
        }
        CP_COMMIT;
    };

    const uint32_t kOff =
        (uint32_t)((((lane & 7) + (lane >> 4) * 8) * KSTR + ((lane >> 3) & 1) * 8) * 2);
    const uint32_t vOff =
        (uint32_t)((((lane & 7) + (lane >> 4) * 8) * VSTR + ((lane >> 3) & 1) * 8) * 2);

    issue(0); issue(1);
    const int NT = Lq / 64;
    for (int kt = 0; kt < NT; kt++) {
        const int b = kt & (FNST - 1);
        if (kt + 2 < NT) { issue(kt + 2); CP_WAIT(2); }
        else if (kt + 1 < NT) { CP_WAIT(1); }
        else { CP_WAIT(0); }
        __syncthreads();

        const uint32_t stK = sB + (uint32_t)(b * 64 * KSTR * 2);
        const uint32_t stV = sB + (uint32_t)((FNST * 64 * KSTR + b * 128 * VSTR) * 2);

        float s[8][4];
        #pragma unroll
        for (int j = 0; j < 8; j++) { s[j][0] = s[j][1] = s[j][2] = s[j][3] = 0.f; }
        #pragma unroll
        for (int ks = 0; ks < 8; ks++) {
            uint32_t kf[8][2];
            #pragma unroll
            for (int jj = 0; jj < 4; jj++)
                ldsm4(kf[2 * jj][0], kf[2 * jj][1], kf[2 * jj + 1][0], kf[2 * jj + 1][1],
                      stK + kOff + jj * 16 * KSTR * 2 + ks * 32);
            #pragma unroll
            for (int j = 0; j < 8; j++)
                mma16(s[j], qf[ks], kf[j][0], kf[j][1]);
        }

        float mx0 = -1e30f, mx1 = -1e30f;
        #pragma unroll
        for (int j = 0; j < 8; j++) {
            mx0 = fmaxf(mx0, fmaxf(s[j][0], s[j][1]));
            mx1 = fmaxf(mx1, fmaxf(s[j][2], s[j][3]));
        }
        mx0 *= KS2; mx1 *= KS2;
        mx0 = fmaxf(mx0, __shfl_xor_sync(0xffffffffu, mx0, 1));
        mx0 = fmaxf(mx0, __shfl_xor_sync(0xffffffffu, mx0, 2));
        mx1 = fmaxf(mx1, __shfl_xor_sync(0xffffffffu, mx1, 1));
        mx1 = fmaxf(mx1, __shfl_xor_sync(0xffffffffu, mx1, 2));
        float nm0 = fmaxf(m0, mx0), nm1 = fmaxf(m1, mx1);
        float corr0 = ex2f(m0 - nm0), corr1 = ex2f(m1 - nm1);
        m0 = nm0; m1 = nm1;
        float r0 = 0.f, r1 = 0.f;
        uint32_t ph[8][2];
        #pragma unroll
        for (int j = 0; j < 8; j++) {
            float p00 = ex2f(s[j][0] * KS2 - m0);
            float p01 = ex2f(s[j][1] * KS2 - m0);
            float p10 = ex2f(s[j][2] * KS2 - m1);
            float p11 = ex2f(s[j][3] * KS2 - m1);
            r0 += p00 + p01; r1 += p10 + p11;
            ph[j][0] = packh2(p00, p01);
            ph[j][1] = packh2(p10, p11);
        }
        r0 += __shfl_xor_sync(0xffffffffu, r0, 1);
        r0 += __shfl_xor_sync(0xffffffffu, r0, 2);
        r1 += __shfl_xor_sync(0xffffffffu, r1, 1);
        r1 += __shfl_xor_sync(0xffffffffu, r1, 2);
        l0 = l0 * corr0 + r0;
        l1 = l1 * corr1 + r1;
        #pragma unroll
        for (int j = 0; j < 16; j++) {
            o[j][0] *= corr0; o[j][1] *= corr0;
            o[j][2] *= corr1; o[j][3] *= corr1;
        }

        #pragma unroll
        for (int mm = 0; mm < 4; mm++) {
            uint32_t a[4] = { ph[2 * mm][0], ph[2 * mm][1],
                              ph[2 * mm + 1][0], ph[2 * mm + 1][1] };
            #pragma unroll
            for (int jj = 0; jj < 8; jj++) {
                uint32_t v0, v1, v2, v3;
                ldsm4(v0, v1, v2, v3, stV + vOff + jj * 16 * VSTR * 2 + mm * 32);
                mma16(o[2 * jj], a, v0, v1);
                mma16(o[2 * jj + 1], a, v2, v3);
            }
        }
    }

    const float inv0 = 1.f / l0, inv1 = 1.f / l1;
    __half* O0 = O + (size_t)(q0 + wid * 16 + g) * Dm + head * HDim + 2 * t4;
    __half* O1 = O0 + 8 * (size_t)Dm;
    #pragma unroll
    for (int j = 0; j < 16; j++) {
        *(__half2*)(O0 + j * 8) = __floats2half2_rn(o[j][0] * inv0, o[j][1] * inv0);
        *(__half2*)(O1 + j * 8) = __floats2half2_rn(o[j][2] * inv1, o[j][3] * inv1);
    }
}

// ---------------------------------------------------------------------------
// Launch
// ---------------------------------------------------------------------------
extern "C" void kernel_launch(void* const* d_in, const int* in_sizes, int n_in,
                              void* d_out, int out_size)
{
    const float* x    = (const float*)d_in[0];
    const float* wq   = (const float*)d_in[1];
    const float* wk   = (const float*)d_in[2];
    const float* wv   = (const float*)d_in[3];
    const float* wo   = (const float*)d_in[4];
    const float* bq   = (const float*)d_in[5];
    const float* bk   = (const float*)d_in[6];
    const float* bv   = (const float*)d_in[7];
    const float* bo   = (const float*)d_in[8];
    const float* gq   = (const float*)d_in[9];
    const float* gk   = (const float*)d_in[10];
    const float* fcos = (const float*)d_in[11];
    const float* fsin = (const float*)d_in[12];
    // d_in[13] = seq_lens (all == L)
    const int* pH = (const int*)d_in[15];
    const int* pW = (const int*)d_in[16];
    float* out = (float*)d_out;

    __half *Xh, *Wc, *Woh, *Qh, *Kh, *Vt, *Ah;
    cudaGetSymbolAddress((void**)&Xh, g_Xh);
    cudaGetSymbolAddress((void**)&Wc, g_Wc);
    cudaGetSymbolAddress((void**)&Woh, g_Woh);
    cudaGetSymbolAddress((void**)&Qh, g_Qh);
    cudaGetSymbolAddress((void**)&Kh, g_Kh);
    cudaGetSymbolAddress((void**)&Vt, g_Vt);
    cudaGetSymbolAddress((void**)&Ah, g_Ah);

    cudaFuncSetAttribute(gemm_qkv, cudaFuncAttributeMaxDynamicSharedMemorySize, G_SMEM);
    cudaFuncSetAttribute(gemm_o, cudaFuncAttributeMaxDynamicSharedMemorySize, G_SMEM);
    cudaFuncSetAttribute(flash_h, cudaFuncAttributeMaxDynamicSharedMemorySize, FL_SMEM);

    const int nX = Lq * Dm, nW = Dm * Dm;
    conv_all<<<dim3(nX / 8 / 256, 5), 256>>>(
        x, wq, wk, wv, wo, Xh,
        Wc, Wc + (size_t)Dm * Dm, Wc + 2 * (size_t)Dm * Dm, Woh, nX, nW);

    gemm_qkv<<<dim3(3 * Dm / 128, Lq / 128), 256, G_SMEM>>>(
        Xh, Wc, bq, bk, bv, Qh, Kh, Vt);

    rmsnorm_rope_h<<<Lq, 256>>>(Qh, Kh, gq, gk, fcos, fsin, pH, pW);

    flash_h<<<dim3(Lq / 128, NH), 256, FL_SMEM>>>(Qh, Kh, Vt, Ah);

    gemm_o<<<dim3(Dm / 128, Lq / 128), 256, G_SMEM>>>(Ah, Woh, bo, out);
}